// round 8
// baseline (speedup 1.0000x reference)
#include <cuda_runtime.h>
#include <cuda_bf16.h>

// Problem constants (from reference)
#define BB 16
#define NN 4096
#define EE 65536
#define D_IN 128
#define D1 256
#define D2 256
#define D3 128
#define MAXDEG 96

// Scratch buffers (device globals; no allocation allowed)
__device__ float g_bufH[(size_t)BB * NN * 256];   // GEMM output (h)
__device__ float g_bufA[(size_t)BB * NN * 256];   // gather output (next layer input)
__device__ int   g_cursor[BB * NN];               // per-(b,v) valid in-degree
__device__ int2  g_payload[(size_t)BB * NN * MAXDEG]; // {u, w_bits} per slot

// ---------------------------------------------------------------------------
// GEMM: H[M, Nd] = X[M, K] @ W[K, Nd]
// BM=BN=128, BK=8, 256 threads, 8x8 micro-tile per thread.
// Double-buffered smem, register prefetch, ONE __syncthreads per K-step.
// ---------------------------------------------------------------------------
#define GBM 128
#define GBN 128
#define GBK 8

__global__ __launch_bounds__(256) void gemm_kernel(
    const float* __restrict__ X, const float* __restrict__ W,
    float* __restrict__ H, int M, int K, int Nd)
{
    __shared__ __align__(16) float sA[2][GBK][GBM + 4];  // transposed, padded
    __shared__ __align__(16) float sB[2][GBK][GBN];

    const int tid = threadIdx.x;
    const int tx = tid & 15;           // 0..15 -> column group
    const int ty = tid >> 4;           // 0..15 -> row group
    const long rowBase = (long)blockIdx.y * GBM;
    const int  colBase = blockIdx.x * GBN;

    const int aRow = tid >> 1;         // 0..127
    const int aK   = (tid & 1) << 2;   // 0 or 4
    const int bRow = tid >> 5;         // 0..7
    const int bCol = (tid & 31) << 2;  // 0..124

    const float* Aptr = X + (rowBase + aRow) * (size_t)K + aK;
    const float* Bptr = W + (size_t)bRow * Nd + colBase + bCol;

    float acc[8][8] = {};

    // Prologue: load tile 0 into buffer 0
    {
        float4 av = *(const float4*)(Aptr);
        sA[0][aK + 0][aRow] = av.x;
        sA[0][aK + 1][aRow] = av.y;
        sA[0][aK + 2][aRow] = av.z;
        sA[0][aK + 3][aRow] = av.w;
        *(float4*)&sB[0][bRow][bCol] = *(const float4*)(Bptr);
    }
    __syncthreads();

    int cur = 0;
    for (int k0 = 0; k0 < K; k0 += GBK) {
        const bool has_next = (k0 + GBK) < K;

        // Prefetch next tile from global into registers (overlaps compute)
        float4 nav, nbv;
        if (has_next) {
            nav = *(const float4*)(Aptr + (k0 + GBK));
            nbv = *(const float4*)(Bptr + (size_t)(k0 + GBK) * Nd);
        }

        // Compute on current buffer
        #pragma unroll
        for (int k = 0; k < GBK; k++) {
            float a[8], b[8];
            *(float4*)&a[0] = *(const float4*)&sA[cur][k][ty * 4];
            *(float4*)&a[4] = *(const float4*)&sA[cur][k][64 + ty * 4];
            *(float4*)&b[0] = *(const float4*)&sB[cur][k][tx * 4];
            *(float4*)&b[4] = *(const float4*)&sB[cur][k][64 + tx * 4];
            #pragma unroll
            for (int i = 0; i < 8; i++)
                #pragma unroll
                for (int j = 0; j < 8; j++)
                    acc[i][j] = fmaf(a[i], b[j], acc[i][j]);
        }

        // Stage next tile into the alternate buffer
        if (has_next) {
            const int nxt = cur ^ 1;
            sA[nxt][aK + 0][aRow] = nav.x;
            sA[nxt][aK + 1][aRow] = nav.y;
            sA[nxt][aK + 2][aRow] = nav.z;
            sA[nxt][aK + 3][aRow] = nav.w;
            *(float4*)&sB[nxt][bRow][bCol] = nbv;
            __syncthreads();
            cur = nxt;
        }
    }

    #pragma unroll
    for (int i = 0; i < 8; i++) {
        const int r = (i < 4) ? (ty * 4 + i) : (64 + ty * 4 + (i - 4));
        float* orow = H + (rowBase + r) * (size_t)Nd + colBase;
        *(float4*)(orow + tx * 4)      = make_float4(acc[i][0], acc[i][1], acc[i][2], acc[i][3]);
        *(float4*)(orow + 64 + tx * 4) = make_float4(acc[i][4], acc[i][5], acc[i][6], acc[i][7]);
    }
}

// ---------------------------------------------------------------------------
// CSR build: zero cursors, then ticket-fill payload slots per destination.
// Edge validity is layer-independent -> build once, reuse 3x.
// ---------------------------------------------------------------------------
__global__ void zero_cursor_kernel(int* __restrict__ cursor)
{
    int idx = blockIdx.x * blockDim.x + threadIdx.x;
    if (idx < BB * NN) cursor[idx] = 0;
}

__global__ __launch_bounds__(256) void fill_kernel(
    const int* __restrict__ ei, const float* __restrict__ ew,
    const int* __restrict__ mask, int* __restrict__ cursor,
    int2* __restrict__ payload)
{
    long idx = (long)blockIdx.x * blockDim.x + threadIdx.x;
    if (idx >= (long)BB * EE) return;
    const int b = (int)(idx >> 16);            // E = 65536
    const int e = (int)(idx & (EE - 1));

    const int u = ei[((size_t)b * 2) * EE + e];
    const int v = ei[((size_t)b * 2 + 1) * EE + e];
    if (mask[b * NN + u] <= 0 || mask[b * NN + v] <= 0) return;
    const float w = ew[(size_t)b * EE + e];

    const int bv = b * NN + v;
    const int slot = atomicAdd(&cursor[bv], 1);
    if (slot < MAXDEG)
        payload[(size_t)bv * MAXDEG + slot] = make_int2(u, __float_as_int(w));
}

// ---------------------------------------------------------------------------
// Gather: one warp per (b,v) destination row. Register accumulation, no
// atomics. Fuses bias, row-mask zeroing, and output ReLU.
// ---------------------------------------------------------------------------
template <int N4>
__global__ __launch_bounds__(256) void gather_kernel(
    const float* __restrict__ H, const int2* __restrict__ payload,
    const int* __restrict__ cursor, const int* __restrict__ mask,
    const float* __restrict__ bias, float* __restrict__ outp)
{
    const int warp = (blockIdx.x * (blockDim.x >> 5)) + (threadIdx.x >> 5);
    const int lane = threadIdx.x & 31;
    if (warp >= BB * NN) return;
    const int bv = warp;

    float4* o4 = (float4*)(outp + (size_t)bv * (N4 * 4));

    if (mask[bv] <= 0) {
        o4[lane] = make_float4(0.f, 0.f, 0.f, 0.f);
        if (N4 == 64) o4[lane + 32] = make_float4(0.f, 0.f, 0.f, 0.f);
        return;
    }

    const float4* b4 = (const float4*)bias;
    float4 acc0 = b4[lane];
    float4 acc1 = (N4 == 64) ? b4[lane + 32] : make_float4(0.f, 0.f, 0.f, 0.f);

    int deg = cursor[bv];
    if (deg > MAXDEG) deg = MAXDEG;
    const int2* pl = payload + (size_t)bv * MAXDEG;
    const int b = bv >> 12;                       // NN = 4096
    const float4* Hb = (const float4*)(H + (size_t)b * NN * (N4 * 4));

    for (int e = 0; e < deg; e++) {
        const int2 p = pl[e];                     // broadcast load
        const int u = p.x;
        const float w = __int_as_float(p.y);
        const float4* hr = Hb + (size_t)u * N4;
        float4 h0 = hr[lane];
        acc0.x = fmaf(w, h0.x, acc0.x);
        acc0.y = fmaf(w, h0.y, acc0.y);
        acc0.z = fmaf(w, h0.z, acc0.z);
        acc0.w = fmaf(w, h0.w, acc0.w);
        if (N4 == 64) {
            float4 h1 = hr[lane + 32];
            acc1.x = fmaf(w, h1.x, acc1.x);
            acc1.y = fmaf(w, h1.y, acc1.y);
            acc1.z = fmaf(w, h1.z, acc1.z);
            acc1.w = fmaf(w, h1.w, acc1.w);
        }
    }

    acc0.x = fmaxf(acc0.x, 0.f); acc0.y = fmaxf(acc0.y, 0.f);
    acc0.z = fmaxf(acc0.z, 0.f); acc0.w = fmaxf(acc0.w, 0.f);
    o4[lane] = acc0;
    if (N4 == 64) {
        acc1.x = fmaxf(acc1.x, 0.f); acc1.y = fmaxf(acc1.y, 0.f);
        acc1.z = fmaxf(acc1.z, 0.f); acc1.w = fmaxf(acc1.w, 0.f);
        o4[lane + 32] = acc1;
    }
}

// ---------------------------------------------------------------------------
extern "C" void kernel_launch(void* const* d_in, const int* in_sizes, int n_in,
                              void* d_out, int out_size)
{
    const float* x    = (const float*)d_in[0];  // [B, N, 128]
    const int*   ei   = (const int*)  d_in[1];  // [B, 2, E]
    const float* ew   = (const float*)d_in[2];  // [B, E]
    const int*   mask = (const int*)  d_in[3];  // [B, N]
    const float* W1   = (const float*)d_in[4];
    const float* b1   = (const float*)d_in[5];
    const float* W2   = (const float*)d_in[6];
    const float* b2   = (const float*)d_in[7];
    const float* W3   = (const float*)d_in[8];
    const float* b3   = (const float*)d_in[9];
    float* out = (float*)d_out;                  // [B, N, 128]

    float* bufH;  float* bufA;  int* cursor;  int2* payload;
    cudaGetSymbolAddress((void**)&bufH, g_bufH);
    cudaGetSymbolAddress((void**)&bufA, g_bufA);
    cudaGetSymbolAddress((void**)&cursor, g_cursor);
    cudaGetSymbolAddress((void**)&payload, g_payload);

    const int M = BB * NN;                       // 65536

    // ---- CSR build (once; edge validity is layer-independent) ----
    zero_cursor_kernel<<<(BB * NN + 255) / 256, 256>>>(cursor);
    fill_kernel<<<(BB * EE + 255) / 256, 256>>>(ei, ew, mask, cursor, payload);

    const int gather_blocks = (BB * NN) / 8;     // 8 warps per 256-thread block

    // ---- Layer 1: h = x @ W1 ; agg1 = relu(gather + b1), masked ----
    {
        dim3 grid(D1 / GBN, M / GBM);
        gemm_kernel<<<grid, 256>>>(x, W1, bufH, M, D_IN, D1);
        gather_kernel<64><<<gather_blocks, 256>>>(bufH, payload, cursor, mask, b1, bufA);
    }
    // ---- Layer 2 ----
    {
        dim3 grid(D2 / GBN, M / GBM);
        gemm_kernel<<<grid, 256>>>(bufA, W2, bufH, M, D1, D2);
        gather_kernel<64><<<gather_blocks, 256>>>(bufH, payload, cursor, mask, b2, bufA);
    }
    // ---- Layer 3: result straight into d_out ----
    {
        dim3 grid(D3 / GBN, M / GBM);
        gemm_kernel<<<grid, 256>>>(bufA, W3, bufH, M, D2, D3);
        gather_kernel<32><<<gather_blocks, 256>>>(bufH, payload, cursor, mask, b3, out);
    }
}

// round 10
// speedup vs baseline: 1.0024x; 1.0024x over previous
#include <cuda_runtime.h>
#include <cuda_bf16.h>

// Problem constants (from reference)
#define BB 16
#define NN 4096
#define EE 65536
#define D_IN 128
#define D1 256
#define D2 256
#define D3 128
#define MAXDEG 96

// Scratch buffers (device globals; no allocation allowed)
__device__ float g_bufH[(size_t)BB * NN * 256];   // GEMM output (h)
__device__ float g_bufA[(size_t)BB * NN * 256];   // gather output (next layer input)
__device__ int   g_cursor[BB * NN];               // per-(b,v) valid in-degree
__device__ int2  g_payload[(size_t)BB * NN * MAXDEG]; // {u, w_bits} per slot

// ---------------------------------------------------------------------------
// GEMM: H[M, Nd] = X[M, K] @ W[K, Nd]
// BM=BN=128, BK=8, 256 threads, 8x8 micro-tile.
// Single-sync double-buffered pipeline; K is a template param so the loop
// fully unrolls and buffer indices are compile-time constants.
// __launch_bounds__(256, 2) pins regs <= 128 so 2 CTAs/SM stay resident.
// ---------------------------------------------------------------------------
#define GBM 128
#define GBN 128
#define GBK 8

template <int K>
__global__ __launch_bounds__(256, 2) void gemm_kernel(
    const float* __restrict__ X, const float* __restrict__ W,
    float* __restrict__ H, int Nd)
{
    __shared__ __align__(16) float sA[2][GBK][GBM + 4];  // transposed, padded
    __shared__ __align__(16) float sB[2][GBK][GBN];

    const int tid = threadIdx.x;
    const int tx = tid & 15;           // 0..15 -> column group
    const int ty = tid >> 4;           // 0..15 -> row group
    const long rowBase = (long)blockIdx.y * GBM;
    const int  colBase = blockIdx.x * GBN;

    const int aRow = tid >> 1;         // 0..127
    const int aK   = (tid & 1) << 2;   // 0 or 4
    const int bRow = tid >> 5;         // 0..7
    const int bCol = (tid & 31) << 2;  // 0..124

    const float* Aptr = X + (rowBase + aRow) * (size_t)K + aK;
    const float* Bptr = W + (size_t)bRow * Nd + colBase + bCol;

    float acc[8][8] = {};

    // Prologue: tile 0 -> buffer 0
    {
        float4 av = *(const float4*)(Aptr);
        sA[0][aK + 0][aRow] = av.x;
        sA[0][aK + 1][aRow] = av.y;
        sA[0][aK + 2][aRow] = av.z;
        sA[0][aK + 3][aRow] = av.w;
        *(float4*)&sB[0][bRow][bCol] = *(const float4*)(Bptr);
    }
    __syncthreads();

    constexpr int T = K / GBK;
    #pragma unroll
    for (int t = 0; t < T; t++) {
        constexpr int UNUSED = 0; (void)UNUSED;
        const int cur = t & 1;

        // Prefetch next tile into registers (issues early; overlaps compute)
        float4 nav, nbv;
        if (t + 1 < T) {
            nav = *(const float4*)(Aptr + (t + 1) * GBK);
            nbv = *(const float4*)(Bptr + (size_t)((t + 1) * GBK) * Nd);
        }

        // Compute on current buffer
        #pragma unroll
        for (int k = 0; k < GBK; k++) {
            float a[8], b[8];
            *(float4*)&a[0] = *(const float4*)&sA[cur][k][ty * 4];
            *(float4*)&a[4] = *(const float4*)&sA[cur][k][64 + ty * 4];
            *(float4*)&b[0] = *(const float4*)&sB[cur][k][tx * 4];
            *(float4*)&b[4] = *(const float4*)&sB[cur][k][64 + tx * 4];
            #pragma unroll
            for (int i = 0; i < 8; i++)
                #pragma unroll
                for (int j = 0; j < 8; j++)
                    acc[i][j] = fmaf(a[i], b[j], acc[i][j]);
        }

        // Stage next tile into alternate buffer; single barrier per step
        if (t + 1 < T) {
            const int nxt = cur ^ 1;
            sA[nxt][aK + 0][aRow] = nav.x;
            sA[nxt][aK + 1][aRow] = nav.y;
            sA[nxt][aK + 2][aRow] = nav.z;
            sA[nxt][aK + 3][aRow] = nav.w;
            *(float4*)&sB[nxt][bRow][bCol] = nbv;
            __syncthreads();
        }
    }

    #pragma unroll
    for (int i = 0; i < 8; i++) {
        const int r = (i < 4) ? (ty * 4 + i) : (64 + ty * 4 + (i - 4));
        float* orow = H + (rowBase + r) * (size_t)Nd + colBase;
        *(float4*)(orow + tx * 4)      = make_float4(acc[i][0], acc[i][1], acc[i][2], acc[i][3]);
        *(float4*)(orow + 64 + tx * 4) = make_float4(acc[i][4], acc[i][5], acc[i][6], acc[i][7]);
    }
}

// ---------------------------------------------------------------------------
// CSR build: zero cursors, then ticket-fill payload slots per destination.
// ---------------------------------------------------------------------------
__global__ void zero_cursor_kernel(int* __restrict__ cursor)
{
    int idx = blockIdx.x * blockDim.x + threadIdx.x;
    if (idx < BB * NN) cursor[idx] = 0;
}

__global__ __launch_bounds__(256) void fill_kernel(
    const int* __restrict__ ei, const float* __restrict__ ew,
    const int* __restrict__ mask, int* __restrict__ cursor,
    int2* __restrict__ payload)
{
    long idx = (long)blockIdx.x * blockDim.x + threadIdx.x;
    if (idx >= (long)BB * EE) return;
    const int b = (int)(idx >> 16);            // E = 65536
    const int e = (int)(idx & (EE - 1));

    const int u = ei[((size_t)b * 2) * EE + e];
    const int v = ei[((size_t)b * 2 + 1) * EE + e];
    if (mask[b * NN + u] <= 0 || mask[b * NN + v] <= 0) return;
    const float w = ew[(size_t)b * EE + e];

    const int bv = b * NN + v;
    const int slot = atomicAdd(&cursor[bv], 1);
    if (slot < MAXDEG)
        payload[(size_t)bv * MAXDEG + slot] = make_int2(u, __float_as_int(w));
}

// ---------------------------------------------------------------------------
// Gather: WPR warps per (b,v) row, each warp owns 32 float4 columns.
// Register accumulation, fuses bias + row-mask + ReLU. Edge loop unrolled
// for memory-level parallelism on the payload/feature loads.
//   N4 = float4s per row: 64 (dout=256, WPR=2) or 32 (dout=128, WPR=1)
// ---------------------------------------------------------------------------
template <int N4, int WPR>
__global__ __launch_bounds__(256) void gather_kernel(
    const float* __restrict__ H, const int2* __restrict__ payload,
    const int* __restrict__ cursor, const int* __restrict__ mask,
    const float* __restrict__ bias, float* __restrict__ outp)
{
    const int gw = (blockIdx.x * (blockDim.x >> 5)) + (threadIdx.x >> 5);
    const int lane = threadIdx.x & 31;
    if (gw >= BB * NN * WPR) return;
    const int bv   = gw / WPR;
    const int part = gw - bv * WPR;
    const int col4 = part * 32 + lane;            // this lane's float4 column

    float4* o4 = (float4*)(outp + (size_t)bv * (N4 * 4));

    if (mask[bv] <= 0) {
        o4[col4] = make_float4(0.f, 0.f, 0.f, 0.f);
        return;
    }

    float4 acc = ((const float4*)bias)[col4];

    int deg = cursor[bv];
    if (deg > MAXDEG) deg = MAXDEG;
    const int2* pl = payload + (size_t)bv * MAXDEG;
    const int b = bv >> 12;                       // NN = 4096
    const float4* Hb = (const float4*)(H + (size_t)b * NN * (N4 * 4)) + col4;

    int e = 0;
    // Unrolled by 4: batch independent payload + feature loads (MLP)
    for (; e + 4 <= deg; e += 4) {
        int2 p0 = pl[e], p1 = pl[e + 1], p2 = pl[e + 2], p3 = pl[e + 3];
        float4 h0 = Hb[(size_t)p0.x * N4];
        float4 h1 = Hb[(size_t)p1.x * N4];
        float4 h2 = Hb[(size_t)p2.x * N4];
        float4 h3 = Hb[(size_t)p3.x * N4];
        float w0 = __int_as_float(p0.y), w1 = __int_as_float(p1.y);
        float w2 = __int_as_float(p2.y), w3 = __int_as_float(p3.y);
        acc.x = fmaf(w0, h0.x, acc.x); acc.y = fmaf(w0, h0.y, acc.y);
        acc.z = fmaf(w0, h0.z, acc.z); acc.w = fmaf(w0, h0.w, acc.w);
        acc.x = fmaf(w1, h1.x, acc.x); acc.y = fmaf(w1, h1.y, acc.y);
        acc.z = fmaf(w1, h1.z, acc.z); acc.w = fmaf(w1, h1.w, acc.w);
        acc.x = fmaf(w2, h2.x, acc.x); acc.y = fmaf(w2, h2.y, acc.y);
        acc.z = fmaf(w2, h2.z, acc.z); acc.w = fmaf(w2, h2.w, acc.w);
        acc.x = fmaf(w3, h3.x, acc.x); acc.y = fmaf(w3, h3.y, acc.y);
        acc.z = fmaf(w3, h3.z, acc.z); acc.w = fmaf(w3, h3.w, acc.w);
    }
    for (; e < deg; e++) {
        int2 p = pl[e];
        float4 h = Hb[(size_t)p.x * N4];
        float w = __int_as_float(p.y);
        acc.x = fmaf(w, h.x, acc.x); acc.y = fmaf(w, h.y, acc.y);
        acc.z = fmaf(w, h.z, acc.z); acc.w = fmaf(w, h.w, acc.w);
    }

    acc.x = fmaxf(acc.x, 0.f); acc.y = fmaxf(acc.y, 0.f);
    acc.z = fmaxf(acc.z, 0.f); acc.w = fmaxf(acc.w, 0.f);
    o4[col4] = acc;
}

// ---------------------------------------------------------------------------
extern "C" void kernel_launch(void* const* d_in, const int* in_sizes, int n_in,
                              void* d_out, int out_size)
{
    const float* x    = (const float*)d_in[0];  // [B, N, 128]
    const int*   ei   = (const int*)  d_in[1];  // [B, 2, E]
    const float* ew   = (const float*)d_in[2];  // [B, E]
    const int*   mask = (const int*)  d_in[3];  // [B, N]
    const float* W1   = (const float*)d_in[4];
    const float* b1   = (const float*)d_in[5];
    const float* W2   = (const float*)d_in[6];
    const float* b2   = (const float*)d_in[7];
    const float* W3   = (const float*)d_in[8];
    const float* b3   = (const float*)d_in[9];
    float* out = (float*)d_out;                  // [B, N, 128]

    float* bufH;  float* bufA;  int* cursor;  int2* payload;
    cudaGetSymbolAddress((void**)&bufH, g_bufH);
    cudaGetSymbolAddress((void**)&bufA, g_bufA);
    cudaGetSymbolAddress((void**)&cursor, g_cursor);
    cudaGetSymbolAddress((void**)&payload, g_payload);

    const int M = BB * NN;                       // 65536

    // ---- CSR build (once; edge validity is layer-independent) ----
    zero_cursor_kernel<<<(BB * NN + 255) / 256, 256>>>(cursor);
    fill_kernel<<<(BB * EE + 255) / 256, 256>>>(ei, ew, mask, cursor, payload);

    const int g256_blocks = (BB * NN * 2) / 8;   // WPR=2 rows, 8 warps/block
    const int g128_blocks = (BB * NN) / 8;       // WPR=1

    // ---- Layer 1: h = x @ W1 ; agg1 = relu(gather + b1), masked ----
    {
        dim3 grid(D1 / GBN, M / GBM);
        gemm_kernel<D_IN><<<grid, 256>>>(x, W1, bufH, D1);
        gather_kernel<64, 2><<<g256_blocks, 256>>>(bufH, payload, cursor, mask, b1, bufA);
    }
    // ---- Layer 2 ----
    {
        dim3 grid(D2 / GBN, M / GBM);
        gemm_kernel<D1><<<grid, 256>>>(bufA, W2, bufH, D2);
        gather_kernel<64, 2><<<g256_blocks, 256>>>(bufH, payload, cursor, mask, b2, bufA);
    }
    // ---- Layer 3: result straight into d_out ----
    {
        dim3 grid(D3 / GBN, M / GBM);
        gemm_kernel<D2><<<grid, 256>>>(bufA, W3, bufH, D3);
        gather_kernel<32, 1><<<g128_blocks, 256>>>(bufH, payload, cursor, mask, b3, out);
    }
}

// round 13
// speedup vs baseline: 1.7580x; 1.7537x over previous
#include <cuda_runtime.h>
#include <cuda_bf16.h>
#include <cstdint>

// Problem constants (from reference)
#define BB 16
#define NN 4096
#define EE 65536
#define D_IN 128
#define D1 256
#define D2 256
#define D3 128
#define MAXDEG 96

// Scratch buffers (device globals; no allocation allowed)
__device__ float g_bufH[(size_t)BB * NN * 256];   // GEMM output (h)
__device__ float g_bufA[(size_t)BB * NN * 256];   // gather output (next layer input)
__device__ int   g_cursor[BB * NN];               // per-(b,v) valid in-degree
__device__ int2  g_payload[(size_t)BB * NN * MAXDEG]; // {u, w_bits} per slot

// ===========================================================================
// Tensor-core GEMM via mma.sync (sm_80+ path; tcgen05 is unavailable because
// the harness emits PTX for plain compute_103).
//
// H[M, ND] = X[M, K] @ W[K, ND] in fp32 accuracy via bf16 split:
//   x = hi + lo (bf16 each); x*w ~= hi*hi' + hi*lo' + lo*hi'   (err ~ 2^-16)
//
// CTA: 128x128 output tile, 256 threads = 8 warps in 4(M) x 2(N) grid.
// Warp tile: 32x64 -> 2(m16) x 8(n8) mma.sync.m16n8k16 fragments, fp32 acc.
// K staged in KC=32 chunks: smem A[hi/lo][128][KC] (k-contig, row pad +2),
// B[hi/lo][128 n][KC] (k-contig transposed, row pad +2).
// ===========================================================================
#define KC 32
#define APAD 2
#define LDK (KC + APAD)     // 34 bf16 per row

__device__ __forceinline__ void mma16816(
    float* d, uint32_t a0, uint32_t a1, uint32_t a2, uint32_t a3,
    uint32_t b0, uint32_t b1)
{
    asm volatile(
        "mma.sync.aligned.m16n8k16.row.col.f32.bf16.bf16.f32 "
        "{%0,%1,%2,%3}, {%4,%5,%6,%7}, {%8,%9}, {%0,%1,%2,%3};"
        : "+f"(d[0]), "+f"(d[1]), "+f"(d[2]), "+f"(d[3])
        : "r"(a0), "r"(a1), "r"(a2), "r"(a3), "r"(b0), "r"(b1));
}

__device__ __forceinline__ void split_bf16(float v, __nv_bfloat16& h, __nv_bfloat16& l)
{
    h = __float2bfloat16_rn(v);
    l = __float2bfloat16_rn(v - __bfloat162float(h));
}

template <int K, int ND>
__global__ __launch_bounds__(256) void tc_gemm_kernel(
    const float* __restrict__ X, const float* __restrict__ W,
    float* __restrict__ H)
{
    __shared__ __align__(16) __nv_bfloat16 sA[2][128][LDK];
    __shared__ __align__(16) __nv_bfloat16 sB[2][128][LDK];

    const int tid  = threadIdx.x;
    const int w    = tid >> 5;
    const int lane = tid & 31;
    const int gid  = lane >> 2;        // group id 0..7
    const int tig  = lane & 3;         // thread in group 0..3
    const int warpM = w & 3;           // 0..3 -> M offset *32
    const int warpN = w >> 2;          // 0..1 -> N offset *64

    const long rowBase = (long)blockIdx.y * 128;
    const int  colBase = blockIdx.x * 128;

    float acc[2][8][4];
    #pragma unroll
    for (int mi = 0; mi < 2; mi++)
        #pragma unroll
        for (int ni = 0; ni < 8; ni++)
            #pragma unroll
            for (int q = 0; q < 4; q++) acc[mi][ni][q] = 0.f;

    constexpr int NCHUNK = K / KC;

    for (int c = 0; c < NCHUNK; c++) {
        const int k0 = c * KC;

        // ---- Stage A chunk: X[rowBase..+127][k0..+31] -> hi/lo bf16 ----
        // 128 rows x 8 float4 = 1024 float4, 4 per thread.
        #pragma unroll
        for (int i = 0; i < 4; i++) {
            const int idx = tid + i * 256;
            const int r  = idx >> 3;
            const int kq = (idx & 7) << 2;
            float4 v = *(const float4*)(X + (rowBase + r) * (size_t)K + k0 + kq);
            __nv_bfloat16 h0, l0, h1, l1, h2, l2, h3, l3;
            split_bf16(v.x, h0, l0); split_bf16(v.y, h1, l1);
            split_bf16(v.z, h2, l2); split_bf16(v.w, h3, l3);
            *(__nv_bfloat162*)&sA[0][r][kq]     = __nv_bfloat162(h0, h1);
            *(__nv_bfloat162*)&sA[0][r][kq + 2] = __nv_bfloat162(h2, h3);
            *(__nv_bfloat162*)&sA[1][r][kq]     = __nv_bfloat162(l0, l1);
            *(__nv_bfloat162*)&sA[1][r][kq + 2] = __nv_bfloat162(l2, l3);
        }

        // ---- Stage B chunk transposed: sB[n][k] = W[k0+k][colBase+n] ----
        // 32 k-rows x 32 float4 = 1024 float4, 4 per thread.
        #pragma unroll
        for (int i = 0; i < 4; i++) {
            const int idx = tid + i * 256;
            const int kr = idx >> 5;
            const int n  = (idx & 31) << 2;
            float4 v = *(const float4*)(W + (size_t)(k0 + kr) * ND + colBase + n);
            float vv[4] = {v.x, v.y, v.z, v.w};
            #pragma unroll
            for (int j = 0; j < 4; j++) {
                __nv_bfloat16 h, l;
                split_bf16(vv[j], h, l);
                sB[0][n + j][kr] = h;
                sB[1][n + j][kr] = l;
            }
        }

        __syncthreads();

        // ---- 3 passes: hi*hi, hi*lo, lo*hi ----
        #pragma unroll
        for (int pass = 0; pass < 3; pass++) {
            const int selA = (pass == 2) ? 1 : 0;
            const int selB = (pass == 1) ? 1 : 0;
            #pragma unroll
            for (int kk = 0; kk < KC; kk += 16) {
                // A fragments for both m16 tiles of this warp
                uint32_t a[2][4];
                #pragma unroll
                for (int mi = 0; mi < 2; mi++) {
                    const int r0 = warpM * 32 + mi * 16 + gid;
                    const int kb = kk + tig * 2;
                    a[mi][0] = *(const uint32_t*)&sA[selA][r0][kb];
                    a[mi][1] = *(const uint32_t*)&sA[selA][r0 + 8][kb];
                    a[mi][2] = *(const uint32_t*)&sA[selA][r0][kb + 8];
                    a[mi][3] = *(const uint32_t*)&sA[selA][r0 + 8][kb + 8];
                }
                #pragma unroll
                for (int ni = 0; ni < 8; ni++) {
                    const int col = warpN * 64 + ni * 8 + gid;
                    const int kb = kk + tig * 2;
                    uint32_t b0 = *(const uint32_t*)&sB[selB][col][kb];
                    uint32_t b1 = *(const uint32_t*)&sB[selB][col][kb + 8];
                    mma16816(acc[0][ni], a[0][0], a[0][1], a[0][2], a[0][3], b0, b1);
                    mma16816(acc[1][ni], a[1][0], a[1][1], a[1][2], a[1][3], b0, b1);
                }
            }
        }

        __syncthreads();
    }

    // ---- Epilogue: write accumulators to H (fp32) ----
    #pragma unroll
    for (int mi = 0; mi < 2; mi++) {
        const long r0 = rowBase + warpM * 32 + mi * 16 + gid;
        #pragma unroll
        for (int ni = 0; ni < 8; ni++) {
            const int col = colBase + warpN * 64 + ni * 8 + tig * 2;
            *(float2*)(H + r0 * ND + col)       = make_float2(acc[mi][ni][0], acc[mi][ni][1]);
            *(float2*)(H + (r0 + 8) * ND + col) = make_float2(acc[mi][ni][2], acc[mi][ni][3]);
        }
    }
}

// ---------------------------------------------------------------------------
// CSR build: zero cursors, then ticket-fill payload slots per destination.
// ---------------------------------------------------------------------------
__global__ void zero_cursor_kernel(int* __restrict__ cursor)
{
    int idx = blockIdx.x * blockDim.x + threadIdx.x;
    if (idx < BB * NN) cursor[idx] = 0;
}

__global__ __launch_bounds__(256) void fill_kernel(
    const int* __restrict__ ei, const float* __restrict__ ew,
    const int* __restrict__ mask, int* __restrict__ cursor,
    int2* __restrict__ payload)
{
    long idx = (long)blockIdx.x * blockDim.x + threadIdx.x;
    if (idx >= (long)BB * EE) return;
    const int b = (int)(idx >> 16);            // E = 65536
    const int e = (int)(idx & (EE - 1));

    const int u = ei[((size_t)b * 2) * EE + e];
    const int v = ei[((size_t)b * 2 + 1) * EE + e];
    if (mask[b * NN + u] <= 0 || mask[b * NN + v] <= 0) return;
    const float w = ew[(size_t)b * EE + e];

    const int bv = b * NN + v;
    const int slot = atomicAdd(&cursor[bv], 1);
    if (slot < MAXDEG)
        payload[(size_t)bv * MAXDEG + slot] = make_int2(u, __float_as_int(w));
}

// ---------------------------------------------------------------------------
// Gather (proven R6 version): one warp per (b,v) row, register accumulation,
// fuses bias + row-mask zeroing + output ReLU.
// ---------------------------------------------------------------------------
template <int N4>
__global__ __launch_bounds__(256) void gather_kernel(
    const float* __restrict__ H, const int2* __restrict__ payload,
    const int* __restrict__ cursor, const int* __restrict__ mask,
    const float* __restrict__ bias, float* __restrict__ outp)
{
    const int warp = (blockIdx.x * (blockDim.x >> 5)) + (threadIdx.x >> 5);
    const int lane = threadIdx.x & 31;
    if (warp >= BB * NN) return;
    const int bv = warp;

    float4* o4 = (float4*)(outp + (size_t)bv * (N4 * 4));

    if (mask[bv] <= 0) {
        o4[lane] = make_float4(0.f, 0.f, 0.f, 0.f);
        if (N4 == 64) o4[lane + 32] = make_float4(0.f, 0.f, 0.f, 0.f);
        return;
    }

    const float4* b4 = (const float4*)bias;
    float4 acc0 = b4[lane];
    float4 acc1 = (N4 == 64) ? b4[lane + 32] : make_float4(0.f, 0.f, 0.f, 0.f);

    int deg = cursor[bv];
    if (deg > MAXDEG) deg = MAXDEG;
    const int2* pl = payload + (size_t)bv * MAXDEG;
    const int b = bv >> 12;                       // NN = 4096
    const float4* Hb = (const float4*)(H + (size_t)b * NN * (N4 * 4));

    for (int e = 0; e < deg; e++) {
        const int2 p = pl[e];                     // broadcast load
        const int u = p.x;
        const float w = __int_as_float(p.y);
        const float4* hr = Hb + (size_t)u * N4;
        float4 h0 = hr[lane];
        acc0.x = fmaf(w, h0.x, acc0.x);
        acc0.y = fmaf(w, h0.y, acc0.y);
        acc0.z = fmaf(w, h0.z, acc0.z);
        acc0.w = fmaf(w, h0.w, acc0.w);
        if (N4 == 64) {
            float4 h1 = hr[lane + 32];
            acc1.x = fmaf(w, h1.x, acc1.x);
            acc1.y = fmaf(w, h1.y, acc1.y);
            acc1.z = fmaf(w, h1.z, acc1.z);
            acc1.w = fmaf(w, h1.w, acc1.w);
        }
    }

    acc0.x = fmaxf(acc0.x, 0.f); acc0.y = fmaxf(acc0.y, 0.f);
    acc0.z = fmaxf(acc0.z, 0.f); acc0.w = fmaxf(acc0.w, 0.f);
    o4[lane] = acc0;
    if (N4 == 64) {
        acc1.x = fmaxf(acc1.x, 0.f); acc1.y = fmaxf(acc1.y, 0.f);
        acc1.z = fmaxf(acc1.z, 0.f); acc1.w = fmaxf(acc1.w, 0.f);
        o4[lane + 32] = acc1;
    }
}

// ---------------------------------------------------------------------------
extern "C" void kernel_launch(void* const* d_in, const int* in_sizes, int n_in,
                              void* d_out, int out_size)
{
    const float* x    = (const float*)d_in[0];  // [B, N, 128]
    const int*   ei   = (const int*)  d_in[1];  // [B, 2, E]
    const float* ew   = (const float*)d_in[2];  // [B, E]
    const int*   mask = (const int*)  d_in[3];  // [B, N]
    const float* W1   = (const float*)d_in[4];
    const float* b1   = (const float*)d_in[5];
    const float* W2   = (const float*)d_in[6];
    const float* b2   = (const float*)d_in[7];
    const float* W3   = (const float*)d_in[8];
    const float* b3   = (const float*)d_in[9];
    float* out = (float*)d_out;                  // [B, N, 128]

    float* bufH;  float* bufA;  int* cursor;  int2* payload;
    cudaGetSymbolAddress((void**)&bufH, g_bufH);
    cudaGetSymbolAddress((void**)&bufA, g_bufA);
    cudaGetSymbolAddress((void**)&cursor, g_cursor);
    cudaGetSymbolAddress((void**)&payload, g_payload);

    const int M = BB * NN;                       // 65536

    // ---- CSR build (once; edge validity is layer-independent) ----
    zero_cursor_kernel<<<(BB * NN + 255) / 256, 256>>>(cursor);
    fill_kernel<<<(BB * EE + 255) / 256, 256>>>(ei, ew, mask, cursor, payload);

    const int gather_blocks = (BB * NN) / 8;     // 8 warps per 256-thread block

    // ---- Layer 1: h = x @ W1 ; agg1 = relu(gather + b1), masked ----
    {
        dim3 grid(D1 / 128, M / 128);
        tc_gemm_kernel<D_IN, D1><<<grid, 256>>>(x, W1, bufH);
        gather_kernel<64><<<gather_blocks, 256>>>(bufH, payload, cursor, mask, b1, bufA);
    }
    // ---- Layer 2 ----
    {
        dim3 grid(D2 / 128, M / 128);
        tc_gemm_kernel<D1, D2><<<grid, 256>>>(bufA, W2, bufH);
        gather_kernel<64><<<gather_blocks, 256>>>(bufH, payload, cursor, mask, b2, bufA);
    }
    // ---- Layer 3: result straight into d_out ----
    {
        dim3 grid(D3 / 128, M / 128);
        tc_gemm_kernel<D2, D3><<<grid, 256>>>(bufA, W3, bufH);
        gather_kernel<32><<<gather_blocks, 256>>>(bufH, payload, cursor, mask, b3, out);
    }
}

// round 14
// speedup vs baseline: 2.4038x; 1.3673x over previous
#include <cuda_runtime.h>
#include <cuda_bf16.h>
#include <cstdint>

// Problem constants (from reference)
#define BB 16
#define NN 4096
#define EE 65536
#define D_IN 128
#define D1 256
#define D2 256
#define D3 128
#define MAXDEG 96

// Scratch buffers (device globals; no allocation allowed)
__device__ float g_bufH[(size_t)BB * NN * 256];            // GEMM output (fp32)
__device__ __nv_bfloat16 g_Ahi[(size_t)BB * NN * 256];     // activation hi (bf16)
__device__ __nv_bfloat16 g_Alo[(size_t)BB * NN * 256];     // activation lo (bf16)
__device__ __nv_bfloat16 g_Wthi[256 * 256];                // W^T hi (per-layer reuse)
__device__ __nv_bfloat16 g_Wtlo[256 * 256];                // W^T lo
__device__ int   g_cursor[BB * NN];                        // per-(b,v) valid in-degree
__device__ int2  g_payload[(size_t)BB * NN * MAXDEG];      // {u, w_bits} per slot

// ===========================================================================
// Helpers
// ===========================================================================
__device__ __forceinline__ void split_bf16(float v, __nv_bfloat16& h, __nv_bfloat16& l)
{
    h = __float2bfloat16_rn(v);
    l = __float2bfloat16_rn(v - __bfloat162float(h));
}

__device__ __forceinline__ uint32_t smem_u32(const void* p) {
    uint32_t a;
    asm("{ .reg .u64 t; cvta.to.shared.u64 t, %1; cvt.u32.u64 %0, t; }"
        : "=r"(a) : "l"(p));
    return a;
}

__device__ __forceinline__ void cpa16(uint32_t dst, const void* src) {
    asm volatile("cp.async.ca.shared.global [%0], [%1], 16;" :: "r"(dst), "l"(src));
}

__device__ __forceinline__ void ldsm_x4(uint32_t* r, uint32_t addr) {
    asm volatile("ldmatrix.sync.aligned.m8n8.x4.shared.b16 {%0,%1,%2,%3}, [%4];"
                 : "=r"(r[0]), "=r"(r[1]), "=r"(r[2]), "=r"(r[3]) : "r"(addr));
}

__device__ __forceinline__ void mma16816(
    float* d, const uint32_t* a, uint32_t b0, uint32_t b1)
{
    asm volatile(
        "mma.sync.aligned.m16n8k16.row.col.f32.bf16.bf16.f32 "
        "{%0,%1,%2,%3}, {%4,%5,%6,%7}, {%8,%9}, {%0,%1,%2,%3};"
        : "+f"(d[0]), "+f"(d[1]), "+f"(d[2]), "+f"(d[3])
        : "r"(a[0]), "r"(a[1]), "r"(a[2]), "r"(a[3]), "r"(b0), "r"(b1));
}

// ===========================================================================
// Tensor-core GEMM: H[M, ND] = A[M, K] @ W[K, ND], A & W^T pre-split bf16.
// A (hi/lo):  [M][K]  row-major, k-contiguous.
// Wt (hi/lo): [ND][K] row-major, k-contiguous (transposed W).
// CTA: 128x128 tile, 8 warps (4M x 2N), warp 32x64; mma.m16n8k16, fp32 acc.
// KC=32 chunks, double-buffered cp.async staging, ldmatrix fragment loads.
// 3 passes: hi*hi + hi*lo + lo*hi  (rel err ~2^-16 per product).
// ===========================================================================
#define KC 32
#define LDKB 40                         // padded row: 40 bf16 = 80 B (16B-mult)
#define SAO(buf, mat, r, k) (((((buf) * 2 + (mat)) * 128 + (r)) * LDKB) + (k))
#define SB_BASE (4 * 128 * LDKB)        // 20480 bf16 elements
#define GEMM_SMEM (2 * SB_BASE * 2)     // 81920 bytes

template <int K, int ND>
__global__ __launch_bounds__(256) void tc_gemm_kernel(
    const __nv_bfloat16* __restrict__ Ahi, const __nv_bfloat16* __restrict__ Alo,
    const __nv_bfloat16* __restrict__ Bhi, const __nv_bfloat16* __restrict__ Blo,
    float* __restrict__ H)
{
    extern __shared__ __align__(16) __nv_bfloat16 sm[];
    const uint32_t smb = smem_u32(sm);

    const int tid  = threadIdx.x;
    const int w    = tid >> 5;
    const int lane = tid & 31;
    const int gid  = lane >> 2;
    const int tig  = lane & 3;
    const int warpM = w & 3;
    const int warpN = w >> 2;

    const long rowBase = (long)blockIdx.y * 128;
    const int  colBase = blockIdx.x * 128;

    float acc[2][8][4];
    #pragma unroll
    for (int mi = 0; mi < 2; mi++)
        #pragma unroll
        for (int ni = 0; ni < 8; ni++)
            #pragma unroll
            for (int q = 0; q < 4; q++) acc[mi][ni][q] = 0.f;

    const __nv_bfloat16* Ag[2] = {Ahi, Alo};
    const __nv_bfloat16* Bg[2] = {Bhi, Blo};

    // Stage one KC chunk into smem buffer `buf` (A and B, hi+lo): 8 cp.async/thread
    auto stage = [&](int buf, int c) {
        const int k0 = c * KC;
        #pragma unroll
        for (int m = 0; m < 2; m++) {
            #pragma unroll
            for (int i = 0; i < 2; i++) {
                const int idx = tid + i * 256;          // 0..511
                const int r = idx >> 2;
                const int p = (idx & 3) * 8;            // k offset within chunk
                cpa16(smb + SAO(buf, m, r, p) * 2,
                      Ag[m] + (rowBase + r) * (size_t)K + k0 + p);
                cpa16(smb + (SB_BASE + SAO(buf, m, r, p)) * 2,
                      Bg[m] + (size_t)(colBase + r) * K + k0 + p);
            }
        }
        asm volatile("cp.async.commit_group;");
    };

    constexpr int T = K / KC;
    stage(0, 0);

    for (int c = 0; c < T; c++) {
        if (c + 1 < T) {
            stage((c + 1) & 1, c + 1);
            asm volatile("cp.async.wait_group 1;");
        } else {
            asm volatile("cp.async.wait_group 0;");
        }
        __syncthreads();

        const int buf = c & 1;
        #pragma unroll
        for (int kk = 0; kk < 2; kk++) {
            const int kb = kk * 16;
            // A fragments (hi and lo) via ldmatrix.x4:
            // lanes 0-15 -> rows r0+lane @ kb; lanes 16-31 -> rows @ kb+8
            uint32_t aF[2][2][4];
            #pragma unroll
            for (int mat = 0; mat < 2; mat++)
                #pragma unroll
                for (int mi = 0; mi < 2; mi++) {
                    const int r = warpM * 32 + mi * 16 + (lane & 15);
                    const int kc = kb + (lane >> 4) * 8;
                    ldsm_x4(aF[mat][mi], smb + SAO(buf, mat, r, kc) * 2);
                }
            // B fragments: x4 covers two n8 tiles; per nip load hi+lo
            #pragma unroll
            for (int nip = 0; nip < 4; nip++) {
                const int n  = warpN * 64 + nip * 16 + (lane & 7) + ((lane >> 4) & 1) * 8;
                const int kc = kb + ((lane >> 3) & 1) * 8;
                uint32_t bh[4], bl[4];
                ldsm_x4(bh, smb + (SB_BASE + SAO(buf, 0, n, kc)) * 2);
                ldsm_x4(bl, smb + (SB_BASE + SAO(buf, 1, n, kc)) * 2);
                #pragma unroll
                for (int mi = 0; mi < 2; mi++) {
                    // hi*hi
                    mma16816(acc[mi][nip * 2],     aF[0][mi], bh[0], bh[1]);
                    mma16816(acc[mi][nip * 2 + 1], aF[0][mi], bh[2], bh[3]);
                    // hi*lo
                    mma16816(acc[mi][nip * 2],     aF[0][mi], bl[0], bl[1]);
                    mma16816(acc[mi][nip * 2 + 1], aF[0][mi], bl[2], bl[3]);
                    // lo*hi
                    mma16816(acc[mi][nip * 2],     aF[1][mi], bh[0], bh[1]);
                    mma16816(acc[mi][nip * 2 + 1], aF[1][mi], bh[2], bh[3]);
                }
            }
        }
        __syncthreads();
    }

    // ---- Epilogue: accumulators -> H (fp32) ----
    #pragma unroll
    for (int mi = 0; mi < 2; mi++) {
        const long r0 = rowBase + warpM * 32 + mi * 16 + gid;
        #pragma unroll
        for (int ni = 0; ni < 8; ni++) {
            const int col = colBase + warpN * 64 + ni * 8 + tig * 2;
            *(float2*)(H + r0 * ND + col)       = make_float2(acc[mi][ni][0], acc[mi][ni][1]);
            *(float2*)(H + (r0 + 8) * ND + col) = make_float2(acc[mi][ni][2], acc[mi][ni][3]);
        }
    }
}

// ---------------------------------------------------------------------------
// One-time splits: x -> (Ahi, Alo) [stride 128]; W[K][ND] -> Wt hi/lo [ND][K]
// ---------------------------------------------------------------------------
__global__ void split_x_kernel(const float* __restrict__ x,
                               __nv_bfloat16* __restrict__ hi,
                               __nv_bfloat16* __restrict__ lo)
{
    long idx = (long)blockIdx.x * blockDim.x + threadIdx.x;     // float4 index
    long total = (long)BB * NN * (D_IN / 4);
    if (idx >= total) return;
    float4 v = ((const float4*)x)[idx];
    __nv_bfloat16 h0, l0, h1, l1, h2, l2, h3, l3;
    split_bf16(v.x, h0, l0); split_bf16(v.y, h1, l1);
    split_bf16(v.z, h2, l2); split_bf16(v.w, h3, l3);
    __nv_bfloat162* ph = (__nv_bfloat162*)(hi + idx * 4);
    ph[0] = __nv_bfloat162(h0, h1); ph[1] = __nv_bfloat162(h2, h3);
    __nv_bfloat162* pl = (__nv_bfloat162*)(lo + idx * 4);
    pl[0] = __nv_bfloat162(l0, l1); pl[1] = __nv_bfloat162(l2, l3);
}

__global__ void split_w_kernel(const float* __restrict__ W, int K, int ND,
                               __nv_bfloat16* __restrict__ hi,
                               __nv_bfloat16* __restrict__ lo)
{
    int idx = blockIdx.x * blockDim.x + threadIdx.x;
    if (idx >= K * ND) return;
    const int n = idx % ND, k = idx / ND;
    __nv_bfloat16 h, l;
    split_bf16(W[idx], h, l);
    hi[(size_t)n * K + k] = h;
    lo[(size_t)n * K + k] = l;
}

// ---------------------------------------------------------------------------
// CSR build: zero cursors, then ticket-fill payload slots per destination.
// ---------------------------------------------------------------------------
__global__ void zero_cursor_kernel(int* __restrict__ cursor)
{
    int idx = blockIdx.x * blockDim.x + threadIdx.x;
    if (idx < BB * NN) cursor[idx] = 0;
}

__global__ __launch_bounds__(256) void fill_kernel(
    const int* __restrict__ ei, const float* __restrict__ ew,
    const int* __restrict__ mask, int* __restrict__ cursor,
    int2* __restrict__ payload)
{
    long idx = (long)blockIdx.x * blockDim.x + threadIdx.x;
    if (idx >= (long)BB * EE) return;
    const int b = (int)(idx >> 16);            // E = 65536
    const int e = (int)(idx & (EE - 1));

    const int u = ei[((size_t)b * 2) * EE + e];
    const int v = ei[((size_t)b * 2 + 1) * EE + e];
    if (mask[b * NN + u] <= 0 || mask[b * NN + v] <= 0) return;
    const float w = ew[(size_t)b * EE + e];

    const int bv = b * NN + v;
    const int slot = atomicAdd(&cursor[bv], 1);
    if (slot < MAXDEG)
        payload[(size_t)bv * MAXDEG + slot] = make_int2(u, __float_as_int(w));
}

// ---------------------------------------------------------------------------
// Gather: one warp per (b,v) row, register accumulation; fuses bias +
// row-mask + ReLU. SPLIT=true -> emit bf16 hi/lo (input of next GEMM);
// SPLIT=false -> emit fp32 (final output).
// ---------------------------------------------------------------------------
template <int N4, bool SPLIT>
__global__ __launch_bounds__(256) void gather_kernel(
    const float* __restrict__ H, const int2* __restrict__ payload,
    const int* __restrict__ cursor, const int* __restrict__ mask,
    const float* __restrict__ bias,
    float* __restrict__ outp,
    __nv_bfloat16* __restrict__ ohi, __nv_bfloat16* __restrict__ olo)
{
    const int warp = (blockIdx.x * (blockDim.x >> 5)) + (threadIdx.x >> 5);
    const int lane = threadIdx.x & 31;
    if (warp >= BB * NN) return;
    const int bv = warp;
    const int D = N4 * 4;

    auto emit = [&](int q4, float4 a) {    // q4: float4 column index
        a.x = fmaxf(a.x, 0.f); a.y = fmaxf(a.y, 0.f);
        a.z = fmaxf(a.z, 0.f); a.w = fmaxf(a.w, 0.f);
        if (SPLIT) {
            __nv_bfloat16 h0, l0, h1, l1, h2, l2, h3, l3;
            split_bf16(a.x, h0, l0); split_bf16(a.y, h1, l1);
            split_bf16(a.z, h2, l2); split_bf16(a.w, h3, l3);
            __nv_bfloat162* ph = (__nv_bfloat162*)(ohi + (size_t)bv * D + q4 * 4);
            ph[0] = __nv_bfloat162(h0, h1); ph[1] = __nv_bfloat162(h2, h3);
            __nv_bfloat162* pl = (__nv_bfloat162*)(olo + (size_t)bv * D + q4 * 4);
            pl[0] = __nv_bfloat162(l0, l1); pl[1] = __nv_bfloat162(l2, l3);
        } else {
            ((float4*)(outp + (size_t)bv * D))[q4] = a;
        }
    };

    if (mask[bv] <= 0) {
        emit(lane, make_float4(0.f, 0.f, 0.f, 0.f));
        if (N4 == 64) emit(lane + 32, make_float4(0.f, 0.f, 0.f, 0.f));
        return;
    }

    const float4* b4 = (const float4*)bias;
    float4 acc0 = b4[lane];
    float4 acc1 = (N4 == 64) ? b4[lane + 32] : make_float4(0.f, 0.f, 0.f, 0.f);

    int deg = cursor[bv];
    if (deg > MAXDEG) deg = MAXDEG;
    const int2* pl = payload + (size_t)bv * MAXDEG;
    const int b = bv >> 12;                       // NN = 4096
    const float4* Hb = (const float4*)(H + (size_t)b * NN * D);

    for (int e = 0; e < deg; e++) {
        const int2 p = pl[e];                     // broadcast load
        const float w = __int_as_float(p.y);
        const float4* hr = Hb + (size_t)p.x * N4;
        float4 h0 = hr[lane];
        acc0.x = fmaf(w, h0.x, acc0.x); acc0.y = fmaf(w, h0.y, acc0.y);
        acc0.z = fmaf(w, h0.z, acc0.z); acc0.w = fmaf(w, h0.w, acc0.w);
        if (N4 == 64) {
            float4 h1 = hr[lane + 32];
            acc1.x = fmaf(w, h1.x, acc1.x); acc1.y = fmaf(w, h1.y, acc1.y);
            acc1.z = fmaf(w, h1.z, acc1.z); acc1.w = fmaf(w, h1.w, acc1.w);
        }
    }

    emit(lane, acc0);
    if (N4 == 64) emit(lane + 32, acc1);
}

// ---------------------------------------------------------------------------
extern "C" void kernel_launch(void* const* d_in, const int* in_sizes, int n_in,
                              void* d_out, int out_size)
{
    const float* x    = (const float*)d_in[0];  // [B, N, 128]
    const int*   ei   = (const int*)  d_in[1];  // [B, 2, E]
    const float* ew   = (const float*)d_in[2];  // [B, E]
    const int*   mask = (const int*)  d_in[3];  // [B, N]
    const float* W1   = (const float*)d_in[4];
    const float* b1   = (const float*)d_in[5];
    const float* W2   = (const float*)d_in[6];
    const float* b2   = (const float*)d_in[7];
    const float* W3   = (const float*)d_in[8];
    const float* b3   = (const float*)d_in[9];
    float* out = (float*)d_out;                  // [B, N, 128]

    float* bufH;  __nv_bfloat16 *Ahi, *Alo, *Wthi, *Wtlo;
    int* cursor;  int2* payload;
    cudaGetSymbolAddress((void**)&bufH, g_bufH);
    cudaGetSymbolAddress((void**)&Ahi, g_Ahi);
    cudaGetSymbolAddress((void**)&Alo, g_Alo);
    cudaGetSymbolAddress((void**)&Wthi, g_Wthi);
    cudaGetSymbolAddress((void**)&Wtlo, g_Wtlo);
    cudaGetSymbolAddress((void**)&cursor, g_cursor);
    cudaGetSymbolAddress((void**)&payload, g_payload);

    const int M = BB * NN;                       // 65536

    cudaFuncSetAttribute(tc_gemm_kernel<D_IN, D1>,
                         cudaFuncAttributeMaxDynamicSharedMemorySize, GEMM_SMEM);
    cudaFuncSetAttribute(tc_gemm_kernel<D1, D2>,
                         cudaFuncAttributeMaxDynamicSharedMemorySize, GEMM_SMEM);
    cudaFuncSetAttribute(tc_gemm_kernel<D2, D3>,
                         cudaFuncAttributeMaxDynamicSharedMemorySize, GEMM_SMEM);

    // ---- CSR build + input splits ----
    zero_cursor_kernel<<<(BB * NN + 255) / 256, 256>>>(cursor);
    fill_kernel<<<(BB * EE + 255) / 256, 256>>>(ei, ew, mask, cursor, payload);
    {
        long t4 = (long)M * (D_IN / 4);
        split_x_kernel<<<(int)((t4 + 255) / 256), 256>>>(x, Ahi, Alo);
    }

    const int gather_blocks = (BB * NN) / 8;     // 8 warps per 256-thread block

    // ---- Layer 1 ----
    split_w_kernel<<<(D_IN * D1 + 255) / 256, 256>>>(W1, D_IN, D1, Wthi, Wtlo);
    {
        dim3 grid(D1 / 128, M / 128);
        tc_gemm_kernel<D_IN, D1><<<grid, 256, GEMM_SMEM>>>(Ahi, Alo, Wthi, Wtlo, bufH);
        gather_kernel<64, true><<<gather_blocks, 256>>>(
            bufH, payload, cursor, mask, b1, nullptr, Ahi, Alo);
    }
    // ---- Layer 2 ----
    split_w_kernel<<<(D1 * D2 + 255) / 256, 256>>>(W2, D1, D2, Wthi, Wtlo);
    {
        dim3 grid(D2 / 128, M / 128);
        tc_gemm_kernel<D1, D2><<<grid, 256, GEMM_SMEM>>>(Ahi, Alo, Wthi, Wtlo, bufH);
        gather_kernel<64, true><<<gather_blocks, 256>>>(
            bufH, payload, cursor, mask, b2, nullptr, Ahi, Alo);
    }
    // ---- Layer 3: fp32 result straight into d_out ----
    split_w_kernel<<<(D2 * D3 + 255) / 256, 256>>>(W3, D2, D3, Wthi, Wtlo);
    {
        dim3 grid(D3 / 128, M / 128);
        tc_gemm_kernel<D2, D3><<<grid, 256, GEMM_SMEM>>>(Ahi, Alo, Wthi, Wtlo, bufH);
        gather_kernel<32, false><<<gather_blocks, 256>>>(
            bufH, payload, cursor, mask, b3, out, nullptr, nullptr);
    }
}

// round 16
// speedup vs baseline: 2.5406x; 1.0569x over previous
#include <cuda_runtime.h>
#include <cuda_bf16.h>
#include <cstdint>

// Problem constants (from reference)
#define BB 16
#define NN 4096
#define EE 65536
#define D_IN 128
#define D1 256
#define D2 256
#define D3 128
#define MAXDEG 96

// Scratch buffers (device globals; no allocation allowed)
__device__ float g_bufH[(size_t)BB * NN * 256];            // GEMM output (fp32)
__device__ __nv_bfloat16 g_Ahi[(size_t)BB * NN * 256];     // activation hi (bf16)
__device__ __nv_bfloat16 g_Alo[(size_t)BB * NN * 256];     // activation lo (bf16)
__device__ __nv_bfloat16 g_Wt1hi[D1 * D_IN], g_Wt1lo[D1 * D_IN];   // [256][128]
__device__ __nv_bfloat16 g_Wt2hi[D2 * D1],   g_Wt2lo[D2 * D1];     // [256][256]
__device__ __nv_bfloat16 g_Wt3hi[D3 * D2],   g_Wt3lo[D3 * D2];     // [128][256]
__device__ int   g_cursor[BB * NN];                        // per-(b,v) valid in-degree
__device__ int2  g_payload[(size_t)BB * NN * MAXDEG];      // {u, w_bits} per slot

// ===========================================================================
// Helpers
// ===========================================================================
__device__ __forceinline__ void split_bf16(float v, __nv_bfloat16& h, __nv_bfloat16& l)
{
    h = __float2bfloat16_rn(v);
    l = __float2bfloat16_rn(v - __bfloat162float(h));
}

__device__ __forceinline__ uint32_t smem_u32(const void* p) {
    uint32_t a;
    asm("{ .reg .u64 t; cvta.to.shared.u64 t, %1; cvt.u32.u64 %0, t; }"
        : "=r"(a) : "l"(p));
    return a;
}

__device__ __forceinline__ void cpa16(uint32_t dst, const void* src) {
    asm volatile("cp.async.ca.shared.global [%0], [%1], 16;" :: "r"(dst), "l"(src));
}

__device__ __forceinline__ void ldsm_x4(uint32_t* r, uint32_t addr) {
    asm volatile("ldmatrix.sync.aligned.m8n8.x4.shared.b16 {%0,%1,%2,%3}, [%4];"
                 : "=r"(r[0]), "=r"(r[1]), "=r"(r[2]), "=r"(r[3]) : "r"(addr));
}

__device__ __forceinline__ void mma16816(
    float* d, const uint32_t* a, uint32_t b0, uint32_t b1)
{
    asm volatile(
        "mma.sync.aligned.m16n8k16.row.col.f32.bf16.bf16.f32 "
        "{%0,%1,%2,%3}, {%4,%5,%6,%7}, {%8,%9}, {%0,%1,%2,%3};"
        : "+f"(d[0]), "+f"(d[1]), "+f"(d[2]), "+f"(d[3])
        : "r"(a[0]), "r"(a[1]), "r"(a[2]), "r"(a[3]), "r"(b0), "r"(b1));
}

// ===========================================================================
// Tensor-core GEMM (proven R13 version): H = A @ W, pre-split bf16.
// CTA 128x128, 8 warps (4Mx2N), mma.m16n8k16 fp32 acc, KC=32 double-buffered
// cp.async staging, ldmatrix fragments, 3 passes (hi*hi + hi*lo + lo*hi).
// ===========================================================================
#define KC 32
#define LDKB 40                         // padded row: 40 bf16 = 80 B (16B-mult)
#define SAO(buf, mat, r, k) (((((buf) * 2 + (mat)) * 128 + (r)) * LDKB) + (k))
#define SB_BASE (4 * 128 * LDKB)        // 20480 bf16 elements
#define GEMM_SMEM (2 * SB_BASE * 2)     // 81920 bytes

template <int K, int ND>
__global__ __launch_bounds__(256) void tc_gemm_kernel(
    const __nv_bfloat16* __restrict__ Ahi, const __nv_bfloat16* __restrict__ Alo,
    const __nv_bfloat16* __restrict__ Bhi, const __nv_bfloat16* __restrict__ Blo,
    float* __restrict__ H)
{
    extern __shared__ __align__(16) __nv_bfloat16 sm[];
    const uint32_t smb = smem_u32(sm);

    const int tid  = threadIdx.x;
    const int w    = tid >> 5;
    const int lane = tid & 31;
    const int gid  = lane >> 2;
    const int tig  = lane & 3;
    const int warpM = w & 3;
    const int warpN = w >> 2;

    const long rowBase = (long)blockIdx.y * 128;
    const int  colBase = blockIdx.x * 128;

    float acc[2][8][4];
    #pragma unroll
    for (int mi = 0; mi < 2; mi++)
        #pragma unroll
        for (int ni = 0; ni < 8; ni++)
            #pragma unroll
            for (int q = 0; q < 4; q++) acc[mi][ni][q] = 0.f;

    const __nv_bfloat16* Ag[2] = {Ahi, Alo};
    const __nv_bfloat16* Bg[2] = {Bhi, Blo};

    auto stage = [&](int buf, int c) {
        const int k0 = c * KC;
        #pragma unroll
        for (int m = 0; m < 2; m++) {
            #pragma unroll
            for (int i = 0; i < 2; i++) {
                const int idx = tid + i * 256;          // 0..511
                const int r = idx >> 2;
                const int p = (idx & 3) * 8;            // k offset within chunk
                cpa16(smb + SAO(buf, m, r, p) * 2,
                      Ag[m] + (rowBase + r) * (size_t)K + k0 + p);
                cpa16(smb + (SB_BASE + SAO(buf, m, r, p)) * 2,
                      Bg[m] + (size_t)(colBase + r) * K + k0 + p);
            }
        }
        asm volatile("cp.async.commit_group;");
    };

    constexpr int T = K / KC;
    stage(0, 0);

    for (int c = 0; c < T; c++) {
        if (c + 1 < T) {
            stage((c + 1) & 1, c + 1);
            asm volatile("cp.async.wait_group 1;");
        } else {
            asm volatile("cp.async.wait_group 0;");
        }
        __syncthreads();

        const int buf = c & 1;
        #pragma unroll
        for (int kk = 0; kk < 2; kk++) {
            const int kb = kk * 16;
            uint32_t aF[2][2][4];
            #pragma unroll
            for (int mat = 0; mat < 2; mat++)
                #pragma unroll
                for (int mi = 0; mi < 2; mi++) {
                    const int r = warpM * 32 + mi * 16 + (lane & 15);
                    const int kc = kb + (lane >> 4) * 8;
                    ldsm_x4(aF[mat][mi], smb + SAO(buf, mat, r, kc) * 2);
                }
            #pragma unroll
            for (int nip = 0; nip < 4; nip++) {
                const int n  = warpN * 64 + nip * 16 + (lane & 7) + ((lane >> 4) & 1) * 8;
                const int kc = kb + ((lane >> 3) & 1) * 8;
                uint32_t bh[4], bl[4];
                ldsm_x4(bh, smb + (SB_BASE + SAO(buf, 0, n, kc)) * 2);
                ldsm_x4(bl, smb + (SB_BASE + SAO(buf, 1, n, kc)) * 2);
                #pragma unroll
                for (int mi = 0; mi < 2; mi++) {
                    mma16816(acc[mi][nip * 2],     aF[0][mi], bh[0], bh[1]);
                    mma16816(acc[mi][nip * 2 + 1], aF[0][mi], bh[2], bh[3]);
                    mma16816(acc[mi][nip * 2],     aF[0][mi], bl[0], bl[1]);
                    mma16816(acc[mi][nip * 2 + 1], aF[0][mi], bl[2], bl[3]);
                    mma16816(acc[mi][nip * 2],     aF[1][mi], bh[0], bh[1]);
                    mma16816(acc[mi][nip * 2 + 1], aF[1][mi], bh[2], bh[3]);
                }
            }
        }
        __syncthreads();
    }

    #pragma unroll
    for (int mi = 0; mi < 2; mi++) {
        const long r0 = rowBase + warpM * 32 + mi * 16 + gid;
        #pragma unroll
        for (int ni = 0; ni < 8; ni++) {
            const int col = colBase + warpN * 64 + ni * 8 + tig * 2;
            *(float2*)(H + r0 * ND + col)       = make_float2(acc[mi][ni][0], acc[mi][ni][1]);
            *(float2*)(H + (r0 + 8) * ND + col) = make_float2(acc[mi][ni][2], acc[mi][ni][3]);
        }
    }
}

// ---------------------------------------------------------------------------
// One-time splits. split_x: x -> (Ahi, Alo). split_w_all: all three W
// matrices -> transposed hi/lo pairs in ONE launch.
// ---------------------------------------------------------------------------
__global__ void split_x_kernel(const float* __restrict__ x,
                               __nv_bfloat16* __restrict__ hi,
                               __nv_bfloat16* __restrict__ lo)
{
    long idx = (long)blockIdx.x * blockDim.x + threadIdx.x;     // float4 index
    long total = (long)BB * NN * (D_IN / 4);
    if (idx >= total) return;
    float4 v = ((const float4*)x)[idx];
    __nv_bfloat16 h0, l0, h1, l1, h2, l2, h3, l3;
    split_bf16(v.x, h0, l0); split_bf16(v.y, h1, l1);
    split_bf16(v.z, h2, l2); split_bf16(v.w, h3, l3);
    __nv_bfloat162* ph = (__nv_bfloat162*)(hi + idx * 4);
    ph[0] = __nv_bfloat162(h0, h1); ph[1] = __nv_bfloat162(h2, h3);
    __nv_bfloat162* pl = (__nv_bfloat162*)(lo + idx * 4);
    pl[0] = __nv_bfloat162(l0, l1); pl[1] = __nv_bfloat162(l2, l3);
}

__device__ __forceinline__ void split_w_one(
    const float* W, int K, int ND, int idx,
    __nv_bfloat16* hi, __nv_bfloat16* lo)
{
    const int n = idx % ND, k = idx / ND;
    __nv_bfloat16 h, l;
    split_bf16(W[idx], h, l);
    hi[(size_t)n * K + k] = h;
    lo[(size_t)n * K + k] = l;
}

__global__ void split_w_all_kernel(
    const float* __restrict__ W1, const float* __restrict__ W2,
    const float* __restrict__ W3,
    __nv_bfloat16* __restrict__ w1h, __nv_bfloat16* __restrict__ w1l,
    __nv_bfloat16* __restrict__ w2h, __nv_bfloat16* __restrict__ w2l,
    __nv_bfloat16* __restrict__ w3h, __nv_bfloat16* __restrict__ w3l)
{
    constexpr int T1 = D_IN * D1;            // 32768
    constexpr int T2 = D1 * D2;              // 65536
    constexpr int T3 = D2 * D3;              // 32768
    int idx = blockIdx.x * blockDim.x + threadIdx.x;
    if (idx < T1) {
        split_w_one(W1, D_IN, D1, idx, w1h, w1l);
    } else if (idx < T1 + T2) {
        split_w_one(W2, D1, D2, idx - T1, w2h, w2l);
    } else if (idx < T1 + T2 + T3) {
        split_w_one(W3, D2, D3, idx - T1 - T2, w3h, w3l);
    }
}

// ---------------------------------------------------------------------------
// CSR build: zero cursors, then ticket-fill payload slots (2 edges/thread).
// ---------------------------------------------------------------------------
__global__ void zero_cursor_kernel(int* __restrict__ cursor)
{
    int idx = blockIdx.x * blockDim.x + threadIdx.x;
    if (idx < BB * NN) cursor[idx] = 0;
}

__global__ __launch_bounds__(256) void fill_kernel(
    const int* __restrict__ ei, const float* __restrict__ ew,
    const int* __restrict__ mask, int* __restrict__ cursor,
    int2* __restrict__ payload)
{
    long t = (long)blockIdx.x * blockDim.x + threadIdx.x;   // edge-pair index
    if (t >= (long)BB * EE / 2) return;
    const int b = (int)(t >> 15);               // E/2 = 32768 pairs per batch
    const int e = (int)(t & (EE / 2 - 1)) * 2;

    const int2 u2 = *(const int2*)(ei + ((size_t)b * 2) * EE + e);
    const int2 v2 = *(const int2*)(ei + ((size_t)b * 2 + 1) * EE + e);
    const float2 w2 = *(const float2*)(ew + (size_t)b * EE + e);
    const int* mb = mask + b * NN;

    #pragma unroll
    for (int j = 0; j < 2; j++) {
        const int u = j ? u2.y : u2.x;
        const int v = j ? v2.y : v2.x;
        if (mb[u] <= 0 || mb[v] <= 0) continue;
        const int bv = b * NN + v;
        const int slot = atomicAdd(&cursor[bv], 1);
        if (slot < MAXDEG)
            payload[(size_t)bv * MAXDEG + slot] =
                make_int2(u, __float_as_int(j ? w2.y : w2.x));
    }
}

// ---------------------------------------------------------------------------
// Gather: one warp per (b,v) row; TWO edges in flight per iteration (payload
// LDGs batched ahead of feature LDGs -> doubled MLP on the latency chain).
// Fuses bias + row-mask + ReLU. SPLIT=true -> emit bf16 hi/lo.
// ---------------------------------------------------------------------------
template <int N4, bool SPLIT>
__global__ __launch_bounds__(256) void gather_kernel(
    const float* __restrict__ H, const int2* __restrict__ payload,
    const int* __restrict__ cursor, const int* __restrict__ mask,
    const float* __restrict__ bias,
    float* __restrict__ outp,
    __nv_bfloat16* __restrict__ ohi, __nv_bfloat16* __restrict__ olo)
{
    const int warp = (blockIdx.x * (blockDim.x >> 5)) + (threadIdx.x >> 5);
    const int lane = threadIdx.x & 31;
    if (warp >= BB * NN) return;
    const int bv = warp;
    const int D = N4 * 4;

    auto emit = [&](int q4, float4 a) {    // q4: float4 column index
        a.x = fmaxf(a.x, 0.f); a.y = fmaxf(a.y, 0.f);
        a.z = fmaxf(a.z, 0.f); a.w = fmaxf(a.w, 0.f);
        if (SPLIT) {
            __nv_bfloat16 h0, l0, h1, l1, h2, l2, h3, l3;
            split_bf16(a.x, h0, l0); split_bf16(a.y, h1, l1);
            split_bf16(a.z, h2, l2); split_bf16(a.w, h3, l3);
            __nv_bfloat162* ph = (__nv_bfloat162*)(ohi + (size_t)bv * D + q4 * 4);
            ph[0] = __nv_bfloat162(h0, h1); ph[1] = __nv_bfloat162(h2, h3);
            __nv_bfloat162* pl = (__nv_bfloat162*)(olo + (size_t)bv * D + q4 * 4);
            pl[0] = __nv_bfloat162(l0, l1); pl[1] = __nv_bfloat162(l2, l3);
        } else {
            ((float4*)(outp + (size_t)bv * D))[q4] = a;
        }
    };

    if (mask[bv] <= 0) {
        emit(lane, make_float4(0.f, 0.f, 0.f, 0.f));
        if (N4 == 64) emit(lane + 32, make_float4(0.f, 0.f, 0.f, 0.f));
        return;
    }

    const float4* b4 = (const float4*)bias;
    float4 acc0 = b4[lane];
    float4 acc1 = (N4 == 64) ? b4[lane + 32] : make_float4(0.f, 0.f, 0.f, 0.f);

    int deg = cursor[bv];
    if (deg > MAXDEG) deg = MAXDEG;
    const int2* pl = payload + (size_t)bv * MAXDEG;
    const int b = bv >> 12;                       // NN = 4096
    const float4* Hb = (const float4*)(H + (size_t)b * NN * D);

    int e = 0;
    for (; e + 2 <= deg; e += 2) {
        const int2 pa = pl[e];
        const int2 pb = pl[e + 1];
        const float4* ra = Hb + (size_t)pa.x * N4;
        const float4* rb = Hb + (size_t)pb.x * N4;
        const float wa = __int_as_float(pa.y);
        const float wb = __int_as_float(pb.y);
        float4 a0 = ra[lane];
        float4 c0 = rb[lane];
        float4 a1, c1;
        if (N4 == 64) { a1 = ra[lane + 32]; c1 = rb[lane + 32]; }
        acc0.x = fmaf(wa, a0.x, acc0.x); acc0.y = fmaf(wa, a0.y, acc0.y);
        acc0.z = fmaf(wa, a0.z, acc0.z); acc0.w = fmaf(wa, a0.w, acc0.w);
        acc0.x = fmaf(wb, c0.x, acc0.x); acc0.y = fmaf(wb, c0.y, acc0.y);
        acc0.z = fmaf(wb, c0.z, acc0.z); acc0.w = fmaf(wb, c0.w, acc0.w);
        if (N4 == 64) {
            acc1.x = fmaf(wa, a1.x, acc1.x); acc1.y = fmaf(wa, a1.y, acc1.y);
            acc1.z = fmaf(wa, a1.z, acc1.z); acc1.w = fmaf(wa, a1.w, acc1.w);
            acc1.x = fmaf(wb, c1.x, acc1.x); acc1.y = fmaf(wb, c1.y, acc1.y);
            acc1.z = fmaf(wb, c1.z, acc1.z); acc1.w = fmaf(wb, c1.w, acc1.w);
        }
    }
    for (; e < deg; e++) {
        const int2 p = pl[e];
        const float w = __int_as_float(p.y);
        const float4* hr = Hb + (size_t)p.x * N4;
        float4 h0 = hr[lane];
        acc0.x = fmaf(w, h0.x, acc0.x); acc0.y = fmaf(w, h0.y, acc0.y);
        acc0.z = fmaf(w, h0.z, acc0.z); acc0.w = fmaf(w, h0.w, acc0.w);
        if (N4 == 64) {
            float4 h1 = hr[lane + 32];
            acc1.x = fmaf(w, h1.x, acc1.x); acc1.y = fmaf(w, h1.y, acc1.y);
            acc1.z = fmaf(w, h1.z, acc1.z); acc1.w = fmaf(w, h1.w, acc1.w);
        }
    }

    emit(lane, acc0);
    if (N4 == 64) emit(lane + 32, acc1);
}

// ---------------------------------------------------------------------------
extern "C" void kernel_launch(void* const* d_in, const int* in_sizes, int n_in,
                              void* d_out, int out_size)
{
    const float* x    = (const float*)d_in[0];  // [B, N, 128]
    const int*   ei   = (const int*)  d_in[1];  // [B, 2, E]
    const float* ew   = (const float*)d_in[2];  // [B, E]
    const int*   mask = (const int*)  d_in[3];  // [B, N]
    const float* W1   = (const float*)d_in[4];
    const float* b1   = (const float*)d_in[5];
    const float* W2   = (const float*)d_in[6];
    const float* b2   = (const float*)d_in[7];
    const float* W3   = (const float*)d_in[8];
    const float* b3   = (const float*)d_in[9];
    float* out = (float*)d_out;                  // [B, N, 128]

    float* bufH;  __nv_bfloat16 *Ahi, *Alo;
    __nv_bfloat16 *w1h, *w1l, *w2h, *w2l, *w3h, *w3l;
    int* cursor;  int2* payload;
    cudaGetSymbolAddress((void**)&bufH, g_bufH);
    cudaGetSymbolAddress((void**)&Ahi, g_Ahi);
    cudaGetSymbolAddress((void**)&Alo, g_Alo);
    cudaGetSymbolAddress((void**)&w1h, g_Wt1hi);
    cudaGetSymbolAddress((void**)&w1l, g_Wt1lo);
    cudaGetSymbolAddress((void**)&w2h, g_Wt2hi);
    cudaGetSymbolAddress((void**)&w2l, g_Wt2lo);
    cudaGetSymbolAddress((void**)&w3h, g_Wt3hi);
    cudaGetSymbolAddress((void**)&w3l, g_Wt3lo);
    cudaGetSymbolAddress((void**)&cursor, g_cursor);
    cudaGetSymbolAddress((void**)&payload, g_payload);

    const int M = BB * NN;                       // 65536

    cudaFuncSetAttribute(tc_gemm_kernel<D_IN, D1>,
                         cudaFuncAttributeMaxDynamicSharedMemorySize, GEMM_SMEM);
    cudaFuncSetAttribute(tc_gemm_kernel<D1, D2>,
                         cudaFuncAttributeMaxDynamicSharedMemorySize, GEMM_SMEM);
    cudaFuncSetAttribute(tc_gemm_kernel<D2, D3>,
                         cudaFuncAttributeMaxDynamicSharedMemorySize, GEMM_SMEM);

    // ---- One-time prep: CSR build, x split, all W splits ----
    zero_cursor_kernel<<<(BB * NN + 255) / 256, 256>>>(cursor);
    fill_kernel<<<(BB * EE / 2 + 255) / 256, 256>>>(ei, ew, mask, cursor, payload);
    {
        long t4 = (long)M * (D_IN / 4);
        split_x_kernel<<<(int)((t4 + 255) / 256), 256>>>(x, Ahi, Alo);
    }
    {
        const int tot = D_IN * D1 + D1 * D2 + D2 * D3;    // 131072
        split_w_all_kernel<<<(tot + 255) / 256, 256>>>(
            W1, W2, W3, w1h, w1l, w2h, w2l, w3h, w3l);
    }

    const int gather_blocks = (BB * NN) / 8;     // 8 warps per 256-thread block

    // ---- Layer 1 ----
    {
        dim3 grid(D1 / 128, M / 128);
        tc_gemm_kernel<D_IN, D1><<<grid, 256, GEMM_SMEM>>>(Ahi, Alo, w1h, w1l, bufH);
        gather_kernel<64, true><<<gather_blocks, 256>>>(
            bufH, payload, cursor, mask, b1, nullptr, Ahi, Alo);
    }
    // ---- Layer 2 ----
    {
        dim3 grid(D2 / 128, M / 128);
        tc_gemm_kernel<D1, D2><<<grid, 256, GEMM_SMEM>>>(Ahi, Alo, w2h, w2l, bufH);
        gather_kernel<64, true><<<gather_blocks, 256>>>(
            bufH, payload, cursor, mask, b2, nullptr, Ahi, Alo);
    }
    // ---- Layer 3: fp32 result straight into d_out ----
    {
        dim3 grid(D3 / 128, M / 128);
        tc_gemm_kernel<D2, D3><<<grid, 256, GEMM_SMEM>>>(Ahi, Alo, w3h, w3l, bufH);
        gather_kernel<32, false><<<gather_blocks, 256>>>(
            bufH, payload, cursor, mask, b3, out, nullptr, nullptr);
    }
}

// round 17
// speedup vs baseline: 3.8974x; 1.5341x over previous
#include <cuda_runtime.h>
#include <cuda_bf16.h>
#include <cstdint>

// Problem constants (from reference)
#define BB 16
#define NN 4096
#define EE 65536
#define D_IN 128
#define D1 256
#define D2 256
#define D3 128
#define MAXDEG 96
#define NROWS (BB * NN)

// Scratch buffers (device globals; no allocation allowed)
__device__ float g_bufH[(size_t)NROWS * 256];              // GEMM output (fp32, compact rows)
__device__ __nv_bfloat16 g_Ahi[(size_t)NROWS * 256];       // activation hi (bf16, compact)
__device__ __nv_bfloat16 g_Alo[(size_t)NROWS * 256];       // activation lo (bf16, compact)
__device__ __nv_bfloat16 g_Wt1hi[D1 * D_IN], g_Wt1lo[D1 * D_IN];   // [256][128]
__device__ __nv_bfloat16 g_Wt2hi[D2 * D1],   g_Wt2lo[D2 * D1];     // [256][256]
__device__ __nv_bfloat16 g_Wt3hi[D3 * D2],   g_Wt3lo[D3 * D2];     // [128][256]
__device__ int   g_count;                                  // # valid rows
__device__ int   g_comp[NROWS];                            // bv -> compact slot (-1 invalid)
__device__ int   g_row[NROWS];                             // compact slot -> bv
__device__ int   g_cursor[NROWS];                          // per-slot valid in-degree
__device__ int2  g_payload[(size_t)NROWS * MAXDEG];        // {cu, w_bits} per slot

// ===========================================================================
// Helpers
// ===========================================================================
__device__ __forceinline__ void split_bf16(float v, __nv_bfloat16& h, __nv_bfloat16& l)
{
    h = __float2bfloat16_rn(v);
    l = __float2bfloat16_rn(v - __bfloat162float(h));
}

__device__ __forceinline__ uint32_t smem_u32(const void* p) {
    uint32_t a;
    asm("{ .reg .u64 t; cvta.to.shared.u64 t, %1; cvt.u32.u64 %0, t; }"
        : "=r"(a) : "l"(p));
    return a;
}

__device__ __forceinline__ void cpa16(uint32_t dst, const void* src) {
    asm volatile("cp.async.ca.shared.global [%0], [%1], 16;" :: "r"(dst), "l"(src));
}

__device__ __forceinline__ void ldsm_x4(uint32_t* r, uint32_t addr) {
    asm volatile("ldmatrix.sync.aligned.m8n8.x4.shared.b16 {%0,%1,%2,%3}, [%4];"
                 : "=r"(r[0]), "=r"(r[1]), "=r"(r[2]), "=r"(r[3]) : "r"(addr));
}

__device__ __forceinline__ void mma16816(
    float* d, const uint32_t* a, uint32_t b0, uint32_t b1)
{
    asm volatile(
        "mma.sync.aligned.m16n8k16.row.col.f32.bf16.bf16.f32 "
        "{%0,%1,%2,%3}, {%4,%5,%6,%7}, {%8,%9}, {%0,%1,%2,%3};"
        : "+f"(d[0]), "+f"(d[1]), "+f"(d[2]), "+f"(d[3])
        : "r"(a[0]), "r"(a[1]), "r"(a[2]), "r"(a[3]), "r"(b0), "r"(b1));
}

// ===========================================================================
// Tensor-core GEMM (proven R13 core) on COMPACT rows: CTAs with
// rowBase >= g_count exit immediately (~half the grid with 50% valid mask).
// Rows in [count, rowBase+128) compute garbage that is never read —
// safe because each output row depends only on its own A row.
// ===========================================================================
#define KC 32
#define LDKB 40                         // padded row: 40 bf16 = 80 B (16B-mult)
#define SAO(buf, mat, r, k) (((((buf) * 2 + (mat)) * 128 + (r)) * LDKB) + (k))
#define SB_BASE (4 * 128 * LDKB)        // 20480 bf16 elements
#define GEMM_SMEM (2 * SB_BASE * 2)     // 81920 bytes

template <int K, int ND>
__global__ __launch_bounds__(256) void tc_gemm_kernel(
    const __nv_bfloat16* __restrict__ Ahi, const __nv_bfloat16* __restrict__ Alo,
    const __nv_bfloat16* __restrict__ Bhi, const __nv_bfloat16* __restrict__ Blo,
    float* __restrict__ H)
{
    const long rowBase = (long)blockIdx.y * 128;
    if (rowBase >= g_count) return;              // compacted: skip empty tiles

    extern __shared__ __align__(16) __nv_bfloat16 sm[];
    const uint32_t smb = smem_u32(sm);

    const int tid  = threadIdx.x;
    const int w    = tid >> 5;
    const int lane = tid & 31;
    const int gid  = lane >> 2;
    const int tig  = lane & 3;
    const int warpM = w & 3;
    const int warpN = w >> 2;

    const int  colBase = blockIdx.x * 128;

    float acc[2][8][4];
    #pragma unroll
    for (int mi = 0; mi < 2; mi++)
        #pragma unroll
        for (int ni = 0; ni < 8; ni++)
            #pragma unroll
            for (int q = 0; q < 4; q++) acc[mi][ni][q] = 0.f;

    const __nv_bfloat16* Ag[2] = {Ahi, Alo};
    const __nv_bfloat16* Bg[2] = {Bhi, Blo};

    auto stage = [&](int buf, int c) {
        const int k0 = c * KC;
        #pragma unroll
        for (int m = 0; m < 2; m++) {
            #pragma unroll
            for (int i = 0; i < 2; i++) {
                const int idx = tid + i * 256;          // 0..511
                const int r = idx >> 2;
                const int p = (idx & 3) * 8;            // k offset within chunk
                cpa16(smb + SAO(buf, m, r, p) * 2,
                      Ag[m] + (rowBase + r) * (size_t)K + k0 + p);
                cpa16(smb + (SB_BASE + SAO(buf, m, r, p)) * 2,
                      Bg[m] + (size_t)(colBase + r) * K + k0 + p);
            }
        }
        asm volatile("cp.async.commit_group;");
    };

    constexpr int T = K / KC;
    stage(0, 0);

    for (int c = 0; c < T; c++) {
        if (c + 1 < T) {
            stage((c + 1) & 1, c + 1);
            asm volatile("cp.async.wait_group 1;");
        } else {
            asm volatile("cp.async.wait_group 0;");
        }
        __syncthreads();

        const int buf = c & 1;
        #pragma unroll
        for (int kk = 0; kk < 2; kk++) {
            const int kb = kk * 16;
            uint32_t aF[2][2][4];
            #pragma unroll
            for (int mat = 0; mat < 2; mat++)
                #pragma unroll
                for (int mi = 0; mi < 2; mi++) {
                    const int r = warpM * 32 + mi * 16 + (lane & 15);
                    const int kc = kb + (lane >> 4) * 8;
                    ldsm_x4(aF[mat][mi], smb + SAO(buf, mat, r, kc) * 2);
                }
            #pragma unroll
            for (int nip = 0; nip < 4; nip++) {
                const int n  = warpN * 64 + nip * 16 + (lane & 7) + ((lane >> 4) & 1) * 8;
                const int kc = kb + ((lane >> 3) & 1) * 8;
                uint32_t bh[4], bl[4];
                ldsm_x4(bh, smb + (SB_BASE + SAO(buf, 0, n, kc)) * 2);
                ldsm_x4(bl, smb + (SB_BASE + SAO(buf, 1, n, kc)) * 2);
                #pragma unroll
                for (int mi = 0; mi < 2; mi++) {
                    mma16816(acc[mi][nip * 2],     aF[0][mi], bh[0], bh[1]);
                    mma16816(acc[mi][nip * 2 + 1], aF[0][mi], bh[2], bh[3]);
                    mma16816(acc[mi][nip * 2],     aF[0][mi], bl[0], bl[1]);
                    mma16816(acc[mi][nip * 2 + 1], aF[0][mi], bl[2], bl[3]);
                    mma16816(acc[mi][nip * 2],     aF[1][mi], bh[0], bh[1]);
                    mma16816(acc[mi][nip * 2 + 1], aF[1][mi], bh[2], bh[3]);
                }
            }
        }
        __syncthreads();
    }

    #pragma unroll
    for (int mi = 0; mi < 2; mi++) {
        const long r0 = rowBase + warpM * 32 + mi * 16 + gid;
        #pragma unroll
        for (int ni = 0; ni < 8; ni++) {
            const int col = colBase + warpN * 64 + ni * 8 + tig * 2;
            *(float2*)(H + r0 * ND + col)       = make_float2(acc[mi][ni][0], acc[mi][ni][1]);
            *(float2*)(H + (r0 + 8) * ND + col) = make_float2(acc[mi][ni][2], acc[mi][ni][3]);
        }
    }
}

// ---------------------------------------------------------------------------
// Compaction + CSR build.
// ---------------------------------------------------------------------------
__global__ void zero_state_kernel(int* __restrict__ cursor)
{
    int idx = blockIdx.x * blockDim.x + threadIdx.x;
    if (idx < NROWS) cursor[idx] = 0;
    if (idx == 0) g_count = 0;
}

__global__ void compact_kernel(const int* __restrict__ mask)
{
    int idx = blockIdx.x * blockDim.x + threadIdx.x;
    if (idx >= NROWS) return;
    if (mask[idx] > 0) {
        int s = atomicAdd(&g_count, 1);
        g_comp[idx] = s;
        g_row[s] = idx;
    } else {
        g_comp[idx] = -1;
    }
}

// Ticket-fill payload; endpoints stored as COMPACT indices (2 edges/thread).
__global__ __launch_bounds__(256) void fill_kernel(
    const int* __restrict__ ei, const float* __restrict__ ew,
    int* __restrict__ cursor, int2* __restrict__ payload)
{
    long t = (long)blockIdx.x * blockDim.x + threadIdx.x;   // edge-pair index
    if (t >= (long)BB * EE / 2) return;
    const int b = (int)(t >> 15);               // E/2 = 32768 pairs per batch
    const int e = (int)(t & (EE / 2 - 1)) * 2;

    const int2 u2 = *(const int2*)(ei + ((size_t)b * 2) * EE + e);
    const int2 v2 = *(const int2*)(ei + ((size_t)b * 2 + 1) * EE + e);
    const float2 w2 = *(const float2*)(ew + (size_t)b * EE + e);

    #pragma unroll
    for (int j = 0; j < 2; j++) {
        const int u = j ? u2.y : u2.x;
        const int v = j ? v2.y : v2.x;
        const int cu = g_comp[b * NN + u];
        const int cv = g_comp[b * NN + v];
        if (cu < 0 || cv < 0) continue;
        const int slot = atomicAdd(&cursor[cv], 1);
        if (slot < MAXDEG)
            payload[(size_t)cv * MAXDEG + slot] =
                make_int2(cu, __float_as_int(j ? w2.y : w2.x));
    }
}

// ---------------------------------------------------------------------------
// One-time splits. split_x: compact rows of x -> (Ahi, Alo).
// ---------------------------------------------------------------------------
__global__ void split_x_kernel(const float* __restrict__ x,
                               __nv_bfloat16* __restrict__ hi,
                               __nv_bfloat16* __restrict__ lo)
{
    long idx = (long)blockIdx.x * blockDim.x + threadIdx.x;     // float4 index
    const int slot = (int)(idx >> 5);            // D_IN/4 = 32 float4 per row
    if (slot >= g_count) return;
    const int q4 = (int)(idx & 31);
    const long src = (long)g_row[slot] * D_IN + q4 * 4;
    float4 v = *(const float4*)(x + src);
    __nv_bfloat16 h0, l0, h1, l1, h2, l2, h3, l3;
    split_bf16(v.x, h0, l0); split_bf16(v.y, h1, l1);
    split_bf16(v.z, h2, l2); split_bf16(v.w, h3, l3);
    __nv_bfloat162* ph = (__nv_bfloat162*)(hi + (size_t)slot * D_IN + q4 * 4);
    ph[0] = __nv_bfloat162(h0, h1); ph[1] = __nv_bfloat162(h2, h3);
    __nv_bfloat162* pl = (__nv_bfloat162*)(lo + (size_t)slot * D_IN + q4 * 4);
    pl[0] = __nv_bfloat162(l0, l1); pl[1] = __nv_bfloat162(l2, l3);
}

__device__ __forceinline__ void split_w_one(
    const float* W, int K, int ND, int idx,
    __nv_bfloat16* hi, __nv_bfloat16* lo)
{
    const int n = idx % ND, k = idx / ND;
    __nv_bfloat16 h, l;
    split_bf16(W[idx], h, l);
    hi[(size_t)n * K + k] = h;
    lo[(size_t)n * K + k] = l;
}

__global__ void split_w_all_kernel(
    const float* __restrict__ W1, const float* __restrict__ W2,
    const float* __restrict__ W3,
    __nv_bfloat16* __restrict__ w1h, __nv_bfloat16* __restrict__ w1l,
    __nv_bfloat16* __restrict__ w2h, __nv_bfloat16* __restrict__ w2l,
    __nv_bfloat16* __restrict__ w3h, __nv_bfloat16* __restrict__ w3l)
{
    constexpr int T1 = D_IN * D1;            // 32768
    constexpr int T2 = D1 * D2;              // 65536
    constexpr int T3 = D2 * D3;              // 32768
    int idx = blockIdx.x * blockDim.x + threadIdx.x;
    if (idx < T1) {
        split_w_one(W1, D_IN, D1, idx, w1h, w1l);
    } else if (idx < T1 + T2) {
        split_w_one(W2, D1, D2, idx - T1, w2h, w2l);
    } else if (idx < T1 + T2 + T3) {
        split_w_one(W3, D2, D3, idx - T1 - T2, w3h, w3l);
    }
}

// ---------------------------------------------------------------------------
// Gather over COMPACT destination slots (all valid): one warp per slot,
// two edges in flight, fuses bias + ReLU. SPLIT=true -> bf16 hi/lo at the
// same compact slot; SPLIT=false -> fp32 at the ORIGINAL row (g_row[slot]).
// ---------------------------------------------------------------------------
template <int N4, bool SPLIT>
__global__ __launch_bounds__(256) void gather_kernel(
    const float* __restrict__ H, const int2* __restrict__ payload,
    const int* __restrict__ cursor,
    const float* __restrict__ bias,
    float* __restrict__ outp,
    __nv_bfloat16* __restrict__ ohi, __nv_bfloat16* __restrict__ olo)
{
    const int slot = (blockIdx.x * (blockDim.x >> 5)) + (threadIdx.x >> 5);
    const int lane = threadIdx.x & 31;
    if (slot >= g_count) return;
    const int D = N4 * 4;

    auto emit = [&](int q4, float4 a) {    // q4: float4 column index
        a.x = fmaxf(a.x, 0.f); a.y = fmaxf(a.y, 0.f);
        a.z = fmaxf(a.z, 0.f); a.w = fmaxf(a.w, 0.f);
        if (SPLIT) {
            __nv_bfloat16 h0, l0, h1, l1, h2, l2, h3, l3;
            split_bf16(a.x, h0, l0); split_bf16(a.y, h1, l1);
            split_bf16(a.z, h2, l2); split_bf16(a.w, h3, l3);
            __nv_bfloat162* ph = (__nv_bfloat162*)(ohi + (size_t)slot * D + q4 * 4);
            ph[0] = __nv_bfloat162(h0, h1); ph[1] = __nv_bfloat162(h2, h3);
            __nv_bfloat162* pl = (__nv_bfloat162*)(olo + (size_t)slot * D + q4 * 4);
            pl[0] = __nv_bfloat162(l0, l1); pl[1] = __nv_bfloat162(l2, l3);
        } else {
            ((float4*)(outp + (size_t)g_row[slot] * D))[q4] = a;
        }
    };

    const float4* b4 = (const float4*)bias;
    float4 acc0 = b4[lane];
    float4 acc1 = (N4 == 64) ? b4[lane + 32] : make_float4(0.f, 0.f, 0.f, 0.f);

    int deg = cursor[slot];
    if (deg > MAXDEG) deg = MAXDEG;
    const int2* pl = payload + (size_t)slot * MAXDEG;
    const float4* Hb = (const float4*)H;

    int e = 0;
    for (; e + 2 <= deg; e += 2) {
        const int2 pa = pl[e];
        const int2 pb = pl[e + 1];
        const float4* ra = Hb + (size_t)pa.x * N4;
        const float4* rb = Hb + (size_t)pb.x * N4;
        const float wa = __int_as_float(pa.y);
        const float wb = __int_as_float(pb.y);
        float4 a0 = ra[lane];
        float4 c0 = rb[lane];
        float4 a1, c1;
        if (N4 == 64) { a1 = ra[lane + 32]; c1 = rb[lane + 32]; }
        acc0.x = fmaf(wa, a0.x, acc0.x); acc0.y = fmaf(wa, a0.y, acc0.y);
        acc0.z = fmaf(wa, a0.z, acc0.z); acc0.w = fmaf(wa, a0.w, acc0.w);
        acc0.x = fmaf(wb, c0.x, acc0.x); acc0.y = fmaf(wb, c0.y, acc0.y);
        acc0.z = fmaf(wb, c0.z, acc0.z); acc0.w = fmaf(wb, c0.w, acc0.w);
        if (N4 == 64) {
            acc1.x = fmaf(wa, a1.x, acc1.x); acc1.y = fmaf(wa, a1.y, acc1.y);
            acc1.z = fmaf(wa, a1.z, acc1.z); acc1.w = fmaf(wa, a1.w, acc1.w);
            acc1.x = fmaf(wb, c1.x, acc1.x); acc1.y = fmaf(wb, c1.y, acc1.y);
            acc1.z = fmaf(wb, c1.z, acc1.z); acc1.w = fmaf(wb, c1.w, acc1.w);
        }
    }
    for (; e < deg; e++) {
        const int2 p = pl[e];
        const float w = __int_as_float(p.y);
        const float4* hr = Hb + (size_t)p.x * N4;
        float4 h0 = hr[lane];
        acc0.x = fmaf(w, h0.x, acc0.x); acc0.y = fmaf(w, h0.y, acc0.y);
        acc0.z = fmaf(w, h0.z, acc0.z); acc0.w = fmaf(w, h0.w, acc0.w);
        if (N4 == 64) {
            float4 h1 = hr[lane + 32];
            acc1.x = fmaf(w, h1.x, acc1.x); acc1.y = fmaf(w, h1.y, acc1.y);
            acc1.z = fmaf(w, h1.z, acc1.z); acc1.w = fmaf(w, h1.w, acc1.w);
        }
    }

    emit(lane, acc0);
    if (N4 == 64) emit(lane + 32, acc1);
}

// ---------------------------------------------------------------------------
// Zero-fill d_out rows for masked-out nodes (one float4 per thread).
// ---------------------------------------------------------------------------
__global__ void zero_invalid_kernel(const int* __restrict__ mask,
                                    float* __restrict__ outp)
{
    long idx = (long)blockIdx.x * blockDim.x + threadIdx.x;     // float4 index
    const int row = (int)(idx >> 5);             // D3/4 = 32 float4 per row
    if (row >= NROWS) return;
    if (mask[row] > 0) return;
    ((float4*)outp)[idx] = make_float4(0.f, 0.f, 0.f, 0.f);
}

// ---------------------------------------------------------------------------
extern "C" void kernel_launch(void* const* d_in, const int* in_sizes, int n_in,
                              void* d_out, int out_size)
{
    const float* x    = (const float*)d_in[0];  // [B, N, 128]
    const int*   ei   = (const int*)  d_in[1];  // [B, 2, E]
    const float* ew   = (const float*)d_in[2];  // [B, E]
    const int*   mask = (const int*)  d_in[3];  // [B, N]
    const float* W1   = (const float*)d_in[4];
    const float* b1   = (const float*)d_in[5];
    const float* W2   = (const float*)d_in[6];
    const float* b2   = (const float*)d_in[7];
    const float* W3   = (const float*)d_in[8];
    const float* b3   = (const float*)d_in[9];
    float* out = (float*)d_out;                  // [B, N, 128]

    float* bufH;  __nv_bfloat16 *Ahi, *Alo;
    __nv_bfloat16 *w1h, *w1l, *w2h, *w2l, *w3h, *w3l;
    int* cursor;  int2* payload;
    cudaGetSymbolAddress((void**)&bufH, g_bufH);
    cudaGetSymbolAddress((void**)&Ahi, g_Ahi);
    cudaGetSymbolAddress((void**)&Alo, g_Alo);
    cudaGetSymbolAddress((void**)&w1h, g_Wt1hi);
    cudaGetSymbolAddress((void**)&w1l, g_Wt1lo);
    cudaGetSymbolAddress((void**)&w2h, g_Wt2hi);
    cudaGetSymbolAddress((void**)&w2l, g_Wt2lo);
    cudaGetSymbolAddress((void**)&w3h, g_Wt3hi);
    cudaGetSymbolAddress((void**)&w3l, g_Wt3lo);
    cudaGetSymbolAddress((void**)&cursor, g_cursor);
    cudaGetSymbolAddress((void**)&payload, g_payload);

    cudaFuncSetAttribute(tc_gemm_kernel<D_IN, D1>,
                         cudaFuncAttributeMaxDynamicSharedMemorySize, GEMM_SMEM);
    cudaFuncSetAttribute(tc_gemm_kernel<D1, D2>,
                         cudaFuncAttributeMaxDynamicSharedMemorySize, GEMM_SMEM);
    cudaFuncSetAttribute(tc_gemm_kernel<D2, D3>,
                         cudaFuncAttributeMaxDynamicSharedMemorySize, GEMM_SMEM);

    // ---- One-time prep: compaction, CSR build, splits ----
    zero_state_kernel<<<(NROWS + 255) / 256, 256>>>(cursor);
    compact_kernel<<<(NROWS + 255) / 256, 256>>>(mask);
    fill_kernel<<<(BB * EE / 2 + 255) / 256, 256>>>(ei, ew, cursor, payload);
    {
        long t4 = (long)NROWS * (D_IN / 4);         // worst-case grid; early exit
        split_x_kernel<<<(int)((t4 + 255) / 256), 256>>>(x, Ahi, Alo);
    }
    {
        const int tot = D_IN * D1 + D1 * D2 + D2 * D3;    // 131072
        split_w_all_kernel<<<(tot + 255) / 256, 256>>>(
            W1, W2, W3, w1h, w1l, w2h, w2l, w3h, w3l);
    }
    zero_invalid_kernel<<<(NROWS * (D3 / 4) + 255) / 256, 256>>>(mask, out);

    const int gather_blocks = NROWS / 8;         // worst-case; early exit

    // ---- Layer 1 ----
    {
        dim3 grid(D1 / 128, NROWS / 128);
        tc_gemm_kernel<D_IN, D1><<<grid, 256, GEMM_SMEM>>>(Ahi, Alo, w1h, w1l, bufH);
        gather_kernel<64, true><<<gather_blocks, 256>>>(
            bufH, payload, cursor, b1, nullptr, Ahi, Alo);
    }
    // ---- Layer 2 ----
    {
        dim3 grid(D2 / 128, NROWS / 128);
        tc_gemm_kernel<D1, D2><<<grid, 256, GEMM_SMEM>>>(Ahi, Alo, w2h, w2l, bufH);
        gather_kernel<64, true><<<gather_blocks, 256>>>(
            bufH, payload, cursor, b2, nullptr, Ahi, Alo);
    }
    // ---- Layer 3: fp32 result into d_out at original row indices ----
    {
        dim3 grid(D3 / 128, NROWS / 128);
        tc_gemm_kernel<D2, D3><<<grid, 256, GEMM_SMEM>>>(Ahi, Alo, w3h, w3l, bufH);
        gather_kernel<32, false><<<gather_blocks, 256>>>(
            bufH, payload, cursor, b3, out, nullptr, nullptr);
    }
}